// round 1
// baseline (speedup 1.0000x reference)
#include <cuda_runtime.h>
#include <math.h>

#define N_B   8
#define SEQ   2048
#define EMB   512
#define H     8
#define HD    64
#define NROWS (N_B*SEQ)   // 16384

// -------- scratch (no cudaMalloc allowed) --------
__device__ float g_q[(size_t)N_B*H*SEQ*HD];   // [n][h][s][d]
__device__ float g_k[(size_t)N_B*H*SEQ*HD];
__device__ float g_v[(size_t)N_B*H*SEQ*HD];
__device__ float g_ao[(size_t)NROWS*EMB];     // [n*s][h*HD+d]

// ============================================================
// Projection GEMM: Y = X @ W  (X:[16384,512], W:[512,512])
// Output written head-split into g_{q,k,v}.
// 128x128x16 tile, 256 threads, 8x8 per thread.
// ============================================================
__global__ __launch_bounds__(256) void proj_kernel(
    const float* __restrict__ values, const float* __restrict__ keys,
    const float* __restrict__ query,
    const float* __restrict__ Wv, const float* __restrict__ Wk,
    const float* __restrict__ Wq)
{
    const int which = blockIdx.z;
    const float* X = (which == 0) ? values : (which == 1) ? keys : query;
    const float* W = (which == 0) ? Wv     : (which == 1) ? Wk   : Wq;
    float* dst     = (which == 0) ? g_v    : (which == 1) ? g_k  : g_q;

    __shared__ float As[16][128];   // A transposed: As[k][m]
    __shared__ float Bs[16][128];   // Bs[k][n]

    const int tid = threadIdx.x;
    const int tx = tid & 15, ty = tid >> 4;
    const int m0 = blockIdx.y * 128;
    const int n0 = blockIdx.x * 128;

    float acc[8][8];
    #pragma unroll
    for (int i = 0; i < 8; i++)
        #pragma unroll
        for (int j = 0; j < 8; j++) acc[i][j] = 0.f;

    for (int k0 = 0; k0 < EMB; k0 += 16) {
        // A tile 128x16 -> transposed
        #pragma unroll
        for (int r = 0; r < 2; r++) {
            int f = tid + 256 * r;         // float4 index 0..511
            int row = f >> 2, c4 = f & 3;
            float4 v = *(const float4*)(X + (size_t)(m0 + row) * EMB + k0 + c4 * 4);
            As[c4*4+0][row] = v.x; As[c4*4+1][row] = v.y;
            As[c4*4+2][row] = v.z; As[c4*4+3][row] = v.w;
        }
        // B tile 16x128
        #pragma unroll
        for (int r = 0; r < 2; r++) {
            int f = tid + 256 * r;
            int row = f >> 5, c4 = f & 31;
            float4 v = *(const float4*)(W + (size_t)(k0 + row) * EMB + n0 + c4 * 4);
            *(float4*)&Bs[row][c4 * 4] = v;
        }
        __syncthreads();
        #pragma unroll
        for (int kk = 0; kk < 16; kk++) {
            float a[8], b[8];
            #pragma unroll
            for (int i = 0; i < 8; i++) a[i] = As[kk][ty * 8 + i];
            #pragma unroll
            for (int j = 0; j < 8; j++) b[j] = Bs[kk][tx * 8 + j];
            #pragma unroll
            for (int i = 0; i < 8; i++)
                #pragma unroll
                for (int j = 0; j < 8; j++)
                    acc[i][j] += a[i] * b[j];
        }
        __syncthreads();
    }

    // write-back, head-split: [((n*H+h)*SEQ + s)*HD + d]
    #pragma unroll
    for (int i = 0; i < 8; i++) {
        int r = m0 + ty * 8 + i;
        int n = r >> 11, s = r & 2047;
        #pragma unroll
        for (int j = 0; j < 8; j++) {
            int c = n0 + tx * 8 + j;
            int h = c >> 6, d = c & 63;
            dst[(((size_t)(n * H + h)) * SEQ + s) * HD + d] = acc[i][j];
        }
    }
}

// ============================================================
// Flash attention, fp32.  BQ=128 queries/block, BKV=64 keys/iter.
// 256 threads, per-thread 8 rows x 4 cols.
// ============================================================
#define BQ  128
#define BKV 64
#define QS  65   // padded smem row stride

__global__ __launch_bounds__(256) void flash_kernel(const int* __restrict__ mask)
{
    extern __shared__ float sm[];
    float* Qs = sm;                   // BQ  * QS
    float* Ks = Qs + BQ * QS;         // BKV * QS
    float* Vs = Ks + BKV * QS;        // BKV * QS
    float* Ps = Vs + BKV * QS;        // BQ  * QS

    const int tid = threadIdx.x;
    const int tx = tid & 15, ty = tid >> 4;
    const int q0 = blockIdx.x * BQ;
    const int nh = blockIdx.y;
    const int n  = nh >> 3;
    const float* Qg = g_q + (size_t)nh * SEQ * HD;
    const float* Kg = g_k + (size_t)nh * SEQ * HD;
    const float* Vg = g_v + (size_t)nh * SEQ * HD;
    const int* mrow = mask + n * SEQ;
    const float scale = 0.125f;       // 1/sqrt(64)

    // load Q tile: 128x64 floats, 8 float4 per thread
    #pragma unroll
    for (int r = 0; r < 8; r++) {
        int f = tid + 256 * r;        // float4 index 0..2047
        int row = f >> 4, c4 = f & 15;
        float4 v = *(const float4*)(Qg + (size_t)(q0 + row) * HD + c4 * 4);
        float* p = Qs + row * QS + c4 * 4;
        p[0] = v.x; p[1] = v.y; p[2] = v.z; p[3] = v.w;
    }

    float acc[8][4], mi[8], li[8];
    #pragma unroll
    for (int i = 0; i < 8; i++) {
        mi[i] = -1e30f; li[i] = 0.f;
        #pragma unroll
        for (int j = 0; j < 4; j++) acc[i][j] = 0.f;
    }
    __syncthreads();

    for (int k0 = 0; k0 < SEQ; k0 += BKV) {
        // load K,V tiles (4 float4 each per thread)
        #pragma unroll
        for (int r = 0; r < 4; r++) {
            int f = tid + 256 * r;     // 0..1023
            int row = f >> 4, c4 = f & 15;
            float4 kv = *(const float4*)(Kg + (size_t)(k0 + row) * HD + c4 * 4);
            float* p = Ks + row * QS + c4 * 4;
            p[0] = kv.x; p[1] = kv.y; p[2] = kv.z; p[3] = kv.w;
            float4 vv = *(const float4*)(Vg + (size_t)(k0 + row) * HD + c4 * 4);
            float* pv = Vs + row * QS + c4 * 4;
            pv[0] = vv.x; pv[1] = vv.y; pv[2] = vv.z; pv[3] = vv.w;
        }
        __syncthreads();

        // S = Q @ K^T   (dot over d)
        float s[8][4];
        #pragma unroll
        for (int i = 0; i < 8; i++)
            #pragma unroll
            for (int j = 0; j < 4; j++) s[i][j] = 0.f;
        #pragma unroll
        for (int kk = 0; kk < HD; kk++) {
            float a[8], b[4];
            #pragma unroll
            for (int i = 0; i < 8; i++) a[i] = Qs[(ty * 8 + i) * QS + kk];
            #pragma unroll
            for (int j = 0; j < 4; j++) b[j] = Ks[(tx * 4 + j) * QS + kk];
            #pragma unroll
            for (int i = 0; i < 8; i++)
                #pragma unroll
                for (int j = 0; j < 4; j++)
                    s[i][j] += a[i] * b[j];
        }

        // mask + scale
        #pragma unroll
        for (int j = 0; j < 4; j++) {
            int mv = mrow[k0 + tx * 4 + j];
            #pragma unroll
            for (int i = 0; i < 8; i++)
                s[i][j] = mv ? s[i][j] * scale : -1e30f;
        }

        // online softmax (rows owned by 16 consecutive lanes)
        #pragma unroll
        for (int i = 0; i < 8; i++) {
            float rmax = fmaxf(fmaxf(s[i][0], s[i][1]), fmaxf(s[i][2], s[i][3]));
            #pragma unroll
            for (int o = 1; o < 16; o <<= 1)
                rmax = fmaxf(rmax, __shfl_xor_sync(0xffffffffu, rmax, o));
            float mnew = fmaxf(mi[i], rmax);
            float corr = __expf(mi[i] - mnew);
            float rsum = 0.f;
            #pragma unroll
            for (int j = 0; j < 4; j++) {
                float p = __expf(s[i][j] - mnew);
                s[i][j] = p; rsum += p;
            }
            #pragma unroll
            for (int o = 1; o < 16; o <<= 1)
                rsum += __shfl_xor_sync(0xffffffffu, rsum, o);
            li[i] = li[i] * corr + rsum;
            mi[i] = mnew;
            #pragma unroll
            for (int j = 0; j < 4; j++) acc[i][j] *= corr;
        }

        // stage P
        #pragma unroll
        for (int i = 0; i < 8; i++)
            #pragma unroll
            for (int j = 0; j < 4; j++)
                Ps[(ty * 8 + i) * QS + tx * 4 + j] = s[i][j];
        __syncthreads();

        // O += P @ V
        #pragma unroll
        for (int kk = 0; kk < BKV; kk++) {
            float a[8], b[4];
            #pragma unroll
            for (int i = 0; i < 8; i++) a[i] = Ps[(ty * 8 + i) * QS + kk];
            #pragma unroll
            for (int j = 0; j < 4; j++) b[j] = Vs[kk * QS + tx * 4 + j];
            #pragma unroll
            for (int i = 0; i < 8; i++)
                #pragma unroll
                for (int j = 0; j < 4; j++)
                    acc[i][j] += a[i] * b[j];
        }
        __syncthreads();
    }

    // epilogue: normalize, write to [n*s][h*HD+d]
    const int h = nh & 7;
    #pragma unroll
    for (int i = 0; i < 8; i++) {
        int srow = q0 + ty * 8 + i;
        float inv = 1.f / li[i];
        #pragma unroll
        for (int j = 0; j < 4; j++) {
            int d = tx * 4 + j;
            g_ao[((size_t)(n * SEQ + srow)) * EMB + h * HD + d] = acc[i][j] * inv;
        }
    }
}

// ============================================================
// Output GEMM: out = g_ao @ Wo + bo
// ============================================================
__global__ __launch_bounds__(256) void out_kernel(
    const float* __restrict__ Wo, const float* __restrict__ bo,
    float* __restrict__ out)
{
    __shared__ float As[16][128];
    __shared__ float Bs[16][128];

    const int tid = threadIdx.x;
    const int tx = tid & 15, ty = tid >> 4;
    const int m0 = blockIdx.y * 128;
    const int n0 = blockIdx.x * 128;

    float acc[8][8];
    #pragma unroll
    for (int i = 0; i < 8; i++)
        #pragma unroll
        for (int j = 0; j < 8; j++) acc[i][j] = 0.f;

    for (int k0 = 0; k0 < EMB; k0 += 16) {
        #pragma unroll
        for (int r = 0; r < 2; r++) {
            int f = tid + 256 * r;
            int row = f >> 2, c4 = f & 3;
            float4 v = *(const float4*)(g_ao + (size_t)(m0 + row) * EMB + k0 + c4 * 4);
            As[c4*4+0][row] = v.x; As[c4*4+1][row] = v.y;
            As[c4*4+2][row] = v.z; As[c4*4+3][row] = v.w;
        }
        #pragma unroll
        for (int r = 0; r < 2; r++) {
            int f = tid + 256 * r;
            int row = f >> 5, c4 = f & 31;
            float4 v = *(const float4*)(Wo + (size_t)(k0 + row) * EMB + n0 + c4 * 4);
            *(float4*)&Bs[row][c4 * 4] = v;
        }
        __syncthreads();
        #pragma unroll
        for (int kk = 0; kk < 16; kk++) {
            float a[8], b[8];
            #pragma unroll
            for (int i = 0; i < 8; i++) a[i] = As[kk][ty * 8 + i];
            #pragma unroll
            for (int j = 0; j < 8; j++) b[j] = Bs[kk][tx * 8 + j];
            #pragma unroll
            for (int i = 0; i < 8; i++)
                #pragma unroll
                for (int j = 0; j < 8; j++)
                    acc[i][j] += a[i] * b[j];
        }
        __syncthreads();
    }

    #pragma unroll
    for (int i = 0; i < 8; i++) {
        size_t r = m0 + ty * 8 + i;
        #pragma unroll
        for (int j = 0; j < 8; j++) {
            int c = n0 + tx * 8 + j;
            out[r * EMB + c] = acc[i][j] + bo[c];
        }
    }
}

// ============================================================
extern "C" void kernel_launch(void* const* d_in, const int* in_sizes, int n_in,
                              void* d_out, int out_size)
{
    const float* values = (const float*)d_in[0];
    const float* keys   = (const float*)d_in[1];
    const float* query  = (const float*)d_in[2];
    const int*   mask   = (const int*)  d_in[3];
    const float* Wv     = (const float*)d_in[4];
    const float* Wk     = (const float*)d_in[5];
    const float* Wq     = (const float*)d_in[6];
    const float* Wo     = (const float*)d_in[7];
    const float* bo     = (const float*)d_in[8];

    // 1) projections (q,k,v head-split)
    dim3 gproj(EMB / 128, NROWS / 128, 3);
    proj_kernel<<<gproj, 256>>>(values, keys, query, Wv, Wk, Wq);

    // 2) flash attention
    size_t smem = (size_t)(BQ * QS + 2 * BKV * QS + BQ * QS) * sizeof(float);
    cudaFuncSetAttribute(flash_kernel, cudaFuncAttributeMaxDynamicSharedMemorySize, (int)smem);
    flash_kernel<<<dim3(SEQ / BQ, N_B * H), 256, smem>>>(mask);

    // 3) output projection + bias
    out_kernel<<<dim3(EMB / 128, NROWS / 128), 256>>>(Wo, bo, (float*)d_out);
}

// round 2
// speedup vs baseline: 1.2456x; 1.2456x over previous
#include <cuda_runtime.h>
#include <math.h>
#include <stdint.h>

#define N_B   8
#define SEQ   2048
#define EMB   512
#define H     8
#define HD    64
#define NROWS (N_B*SEQ)   // 16384

// -------- scratch (no cudaMalloc allowed) --------
__device__ float g_q[(size_t)N_B*H*SEQ*HD];   // [n][h][s][d]
__device__ float g_k[(size_t)N_B*H*SEQ*HD];
__device__ float g_v[(size_t)N_B*H*SEQ*HD];
__device__ float g_ao[(size_t)NROWS*EMB];     // [n*s][h*HD+d]

// ---------------- tf32 helpers ----------------
__device__ __forceinline__ uint32_t f2tf(float x) {
    uint32_t r; asm("cvt.rna.tf32.f32 %0, %1;" : "=r"(r) : "f"(x)); return r;
}
__device__ __forceinline__ void split2(float x, uint32_t &hi, uint32_t &lo) {
    hi = f2tf(x);
    lo = f2tf(x - __uint_as_float(hi));
}
__device__ __forceinline__ void mma8(float c[4], const uint32_t a[4], const uint32_t b[2]) {
    asm volatile(
      "mma.sync.aligned.m16n8k8.row.col.f32.tf32.tf32.f32 "
      "{%0,%1,%2,%3},{%4,%5,%6,%7},{%8,%9},{%0,%1,%2,%3};\n"
      : "+f"(c[0]), "+f"(c[1]), "+f"(c[2]), "+f"(c[3])
      : "r"(a[0]), "r"(a[1]), "r"(a[2]), "r"(a[3]), "r"(b[0]), "r"(b[1]));
}

// ============================================================
// 3xTF32 GEMM tile: C[128x128] = X[128x512-slice] @ W
// 256 threads, 8 warps in 4(m) x 2(n), warp tile 32x64.
// ============================================================
__device__ __forceinline__ void gemm_tile_3t(
    const float* __restrict__ X, const float* __restrict__ W,
    float c[2][8][4], int m0, int n0, int tid)
{
    __shared__ float As[128][36];    // [m][k] pad 36: conflict-free frag loads
    __shared__ float Bs[32][136];    // [k][n] pad 136

    const int lane = tid & 31;
    const int w = tid >> 5;
    const int g = lane >> 2, cq = lane & 3;
    const int wm = (w & 3) * 32, wn = (w >> 2) * 64;

    #pragma unroll
    for (int mt = 0; mt < 2; mt++)
        #pragma unroll
        for (int nt = 0; nt < 8; nt++)
            #pragma unroll
            for (int e = 0; e < 4; e++) c[mt][nt][e] = 0.f;

    for (int k0 = 0; k0 < EMB; k0 += 32) {
        // A tile 128x32
        #pragma unroll
        for (int it = 0; it < 4; it++) {
            int f = tid + 256 * it;            // float4 idx 0..1023
            int row = f >> 3, c4 = f & 7;
            *(float4*)&As[row][c4 * 4] =
                *(const float4*)(X + (size_t)(m0 + row) * EMB + k0 + c4 * 4);
        }
        // B tile 32x128
        #pragma unroll
        for (int it = 0; it < 4; it++) {
            int f = tid + 256 * it;
            int row = f >> 5, c4 = f & 31;
            *(float4*)&Bs[row][c4 * 4] =
                *(const float4*)(W + (size_t)(k0 + row) * EMB + n0 + c4 * 4);
        }
        __syncthreads();

        #pragma unroll
        for (int ks = 0; ks < 4; ks++) {
            const int kk = ks * 8 + cq;
            uint32_t ahi[2][4], alo[2][4];
            #pragma unroll
            for (int mt = 0; mt < 2; mt++) {
                int rb = wm + mt * 16 + g;
                split2(As[rb    ][kk    ], ahi[mt][0], alo[mt][0]);
                split2(As[rb + 8][kk    ], ahi[mt][1], alo[mt][1]);
                split2(As[rb    ][kk + 4], ahi[mt][2], alo[mt][2]);
                split2(As[rb + 8][kk + 4], ahi[mt][3], alo[mt][3]);
            }
            uint32_t bhi[8][2], blo[8][2];
            #pragma unroll
            for (int nt = 0; nt < 8; nt++) {
                int nn = wn + nt * 8 + g;
                split2(Bs[kk    ][nn], bhi[nt][0], blo[nt][0]);
                split2(Bs[kk + 4][nn], bhi[nt][1], blo[nt][1]);
            }
            #pragma unroll
            for (int mt = 0; mt < 2; mt++)
                #pragma unroll
                for (int nt = 0; nt < 8; nt++) {
                    mma8(c[mt][nt], ahi[mt], bhi[nt]);
                    mma8(c[mt][nt], alo[mt], bhi[nt]);
                    mma8(c[mt][nt], ahi[mt], blo[nt]);
                }
        }
        __syncthreads();
    }
}

// ============================================================
// Projections: head-split epilogue
// ============================================================
__global__ __launch_bounds__(256, 1) void proj_kernel(
    const float* __restrict__ values, const float* __restrict__ keys,
    const float* __restrict__ query,
    const float* __restrict__ Wv, const float* __restrict__ Wk,
    const float* __restrict__ Wq)
{
    const int which = blockIdx.z;
    const float* X = (which == 0) ? values : (which == 1) ? keys : query;
    const float* W = (which == 0) ? Wv     : (which == 1) ? Wk   : Wq;
    float* dst     = (which == 0) ? g_v    : (which == 1) ? g_k  : g_q;

    const int m0 = blockIdx.y * 128, n0 = blockIdx.x * 128;
    float c[2][8][4];
    gemm_tile_3t(X, W, c, m0, n0, threadIdx.x);

    const int lane = threadIdx.x & 31, w = threadIdx.x >> 5;
    const int g = lane >> 2, cq = lane & 3;
    const int wm = (w & 3) * 32, wn = (w >> 2) * 64;

    #pragma unroll
    for (int mt = 0; mt < 2; mt++) {
        #pragma unroll
        for (int half = 0; half < 2; half++) {
            int row = m0 + wm + mt * 16 + g + half * 8;
            int n = row >> 11, s = row & 2047;
            #pragma unroll
            for (int nt = 0; nt < 8; nt++) {
                int col = n0 + wn + nt * 8 + 2 * cq;
                int h = col >> 6, d = col & 63;
                float2 v = make_float2(c[mt][nt][half * 2 + 0], c[mt][nt][half * 2 + 1]);
                *(float2*)&dst[(((size_t)(n * H + h)) * SEQ + s) * HD + d] = v;
            }
        }
    }
}

// ============================================================
// Output GEMM: out = g_ao @ Wo + bo
// ============================================================
__global__ __launch_bounds__(256, 1) void out_kernel(
    const float* __restrict__ Wo, const float* __restrict__ bo,
    float* __restrict__ out)
{
    const int m0 = blockIdx.y * 128, n0 = blockIdx.x * 128;
    float c[2][8][4];
    gemm_tile_3t(g_ao, Wo, c, m0, n0, threadIdx.x);

    const int lane = threadIdx.x & 31, w = threadIdx.x >> 5;
    const int g = lane >> 2, cq = lane & 3;
    const int wm = (w & 3) * 32, wn = (w >> 2) * 64;

    #pragma unroll
    for (int mt = 0; mt < 2; mt++) {
        #pragma unroll
        for (int half = 0; half < 2; half++) {
            size_t row = m0 + wm + mt * 16 + g + half * 8;
            #pragma unroll
            for (int nt = 0; nt < 8; nt++) {
                int col = n0 + wn + nt * 8 + 2 * cq;
                float2 v = make_float2(c[mt][nt][half * 2 + 0] + bo[col],
                                       c[mt][nt][half * 2 + 1] + bo[col + 1]);
                *(float2*)&out[row * EMB + col] = v;
            }
        }
    }
}

// ============================================================
// Flash attention, 3xTF32 mma. BQ=256, BKV=64.
// 8 warps; warp w owns q-rows [w*32, w*32+32).
// ============================================================
#define BQF 256
#define BKV 64
#define QST 68
#define VST 72
#define PST 76

__global__ __launch_bounds__(256, 1) void flash_kernel(const int* __restrict__ mask)
{
    extern __shared__ float sm[];
    float* Qs = sm;                        // 256*68
    float* Ks = Qs + BQF * QST;            // 64*68
    float* Vs = Ks + BKV * QST;            // 64*72
    float* Ps = Vs + BKV * VST;            // 256*76
    int*   ms = (int*)(Ps + BQF * PST);    // 64

    const int tid = threadIdx.x;
    const int lane = tid & 31, w = tid >> 5;
    const int g = lane >> 2, cq = lane & 3;
    const int q0 = blockIdx.x * BQF;
    const int nh = blockIdx.y;
    const int n  = nh >> 3, h = nh & 7;
    const float* Qg = g_q + (size_t)nh * SEQ * HD;
    const float* Kg = g_k + (size_t)nh * SEQ * HD;
    const float* Vg = g_v + (size_t)nh * SEQ * HD;
    const int* mrow = mask + n * SEQ;
    const float scale = 0.125f;   // 1/sqrt(64)

    // load Q tile (raw fp32; split at frag load)
    #pragma unroll
    for (int it = 0; it < 16; it++) {
        int f = tid + 256 * it;
        int row = f >> 4, c4 = f & 15;
        *(float4*)&Qs[row * QST + c4 * 4] =
            *(const float4*)(Qg + (size_t)(q0 + row) * HD + c4 * 4);
    }

    float acc[2][8][4];
    float mi[4], li[4];
    #pragma unroll
    for (int i = 0; i < 4; i++) { mi[i] = -1e30f; li[i] = 0.f; }
    #pragma unroll
    for (int mt = 0; mt < 2; mt++)
        #pragma unroll
        for (int nt = 0; nt < 8; nt++)
            #pragma unroll
            for (int e = 0; e < 4; e++) acc[mt][nt][e] = 0.f;
    __syncthreads();

    for (int k0 = 0; k0 < SEQ; k0 += BKV) {
        // load K, V tiles
        #pragma unroll
        for (int it = 0; it < 4; it++) {
            int f = tid + 256 * it;
            int row = f >> 4, c4 = f & 15;
            *(float4*)&Ks[row * QST + c4 * 4] =
                *(const float4*)(Kg + (size_t)(k0 + row) * HD + c4 * 4);
            *(float4*)&Vs[row * VST + c4 * 4] =
                *(const float4*)(Vg + (size_t)(k0 + row) * HD + c4 * 4);
        }
        if (tid < BKV) ms[tid] = mrow[k0 + tid];
        __syncthreads();

        // ---- S = Q @ K^T  (3xTF32) ----
        float s[2][8][4];
        #pragma unroll
        for (int mt = 0; mt < 2; mt++)
            #pragma unroll
            for (int nt = 0; nt < 8; nt++)
                #pragma unroll
                for (int e = 0; e < 4; e++) s[mt][nt][e] = 0.f;

        #pragma unroll
        for (int ks = 0; ks < 8; ks++) {
            const int kk = ks * 8 + cq;
            uint32_t ahi[2][4], alo[2][4];
            #pragma unroll
            for (int mt = 0; mt < 2; mt++) {
                int rb = w * 32 + mt * 16 + g;
                split2(Qs[(rb    ) * QST + kk    ], ahi[mt][0], alo[mt][0]);
                split2(Qs[(rb + 8) * QST + kk    ], ahi[mt][1], alo[mt][1]);
                split2(Qs[(rb    ) * QST + kk + 4], ahi[mt][2], alo[mt][2]);
                split2(Qs[(rb + 8) * QST + kk + 4], ahi[mt][3], alo[mt][3]);
            }
            uint32_t bhi[8][2], blo[8][2];
            #pragma unroll
            for (int nt = 0; nt < 8; nt++) {
                int nn = nt * 8 + g;
                split2(Ks[nn * QST + kk    ], bhi[nt][0], blo[nt][0]);
                split2(Ks[nn * QST + kk + 4], bhi[nt][1], blo[nt][1]);
            }
            #pragma unroll
            for (int mt = 0; mt < 2; mt++)
                #pragma unroll
                for (int nt = 0; nt < 8; nt++) {
                    mma8(s[mt][nt], ahi[mt], bhi[nt]);
                    mma8(s[mt][nt], alo[mt], bhi[nt]);
                    mma8(s[mt][nt], ahi[mt], blo[nt]);
                }
        }

        // ---- mask + scale + online softmax, stage P ----
        #pragma unroll
        for (int mt = 0; mt < 2; mt++) {
            float mx0 = -1e30f, mx1 = -1e30f;
            #pragma unroll
            for (int nt = 0; nt < 8; nt++) {
                #pragma unroll
                for (int j = 0; j < 2; j++) {
                    int col = nt * 8 + 2 * cq + j;
                    int mv = ms[col];
                    float v0 = mv ? s[mt][nt][j]     * scale : -1e30f;
                    float v1 = mv ? s[mt][nt][2 + j] * scale : -1e30f;
                    s[mt][nt][j]     = v0;
                    s[mt][nt][2 + j] = v1;
                    mx0 = fmaxf(mx0, v0);
                    mx1 = fmaxf(mx1, v1);
                }
            }
            mx0 = fmaxf(mx0, __shfl_xor_sync(0xffffffffu, mx0, 1));
            mx0 = fmaxf(mx0, __shfl_xor_sync(0xffffffffu, mx0, 2));
            mx1 = fmaxf(mx1, __shfl_xor_sync(0xffffffffu, mx1, 1));
            mx1 = fmaxf(mx1, __shfl_xor_sync(0xffffffffu, mx1, 2));

            const int i0 = mt * 2, i1 = mt * 2 + 1;
            float mn0 = fmaxf(mi[i0], mx0), mn1 = fmaxf(mi[i1], mx1);
            float cr0 = __expf(mi[i0] - mn0), cr1 = __expf(mi[i1] - mn1);
            float sum0 = 0.f, sum1 = 0.f;
            #pragma unroll
            for (int nt = 0; nt < 8; nt++) {
                #pragma unroll
                for (int j = 0; j < 2; j++) {
                    float p0 = __expf(s[mt][nt][j]     - mn0);
                    float p1 = __expf(s[mt][nt][2 + j] - mn1);
                    s[mt][nt][j] = p0;     sum0 += p0;
                    s[mt][nt][2 + j] = p1; sum1 += p1;
                }
            }
            sum0 += __shfl_xor_sync(0xffffffffu, sum0, 1);
            sum0 += __shfl_xor_sync(0xffffffffu, sum0, 2);
            sum1 += __shfl_xor_sync(0xffffffffu, sum1, 1);
            sum1 += __shfl_xor_sync(0xffffffffu, sum1, 2);
            li[i0] = li[i0] * cr0 + sum0; mi[i0] = mn0;
            li[i1] = li[i1] * cr1 + sum1; mi[i1] = mn1;

            int rb = w * 32 + mt * 16 + g;
            #pragma unroll
            for (int nt = 0; nt < 8; nt++) {
                acc[mt][nt][0] *= cr0; acc[mt][nt][1] *= cr0;
                acc[mt][nt][2] *= cr1; acc[mt][nt][3] *= cr1;
                *(float2*)&Ps[(rb    ) * PST + nt * 8 + 2 * cq] =
                    make_float2(s[mt][nt][0], s[mt][nt][1]);
                *(float2*)&Ps[(rb + 8) * PST + nt * 8 + 2 * cq] =
                    make_float2(s[mt][nt][2], s[mt][nt][3]);
            }
        }
        __syncwarp();   // P tile is warp-local (rows w*32..w*32+31)

        // ---- O += P @ V  (3xTF32) ----
        #pragma unroll
        for (int ks = 0; ks < 8; ks++) {
            const int kk = ks * 8 + cq;
            uint32_t phi[2][4], plo[2][4];
            #pragma unroll
            for (int mt = 0; mt < 2; mt++) {
                int rb = w * 32 + mt * 16 + g;
                split2(Ps[(rb    ) * PST + kk    ], phi[mt][0], plo[mt][0]);
                split2(Ps[(rb + 8) * PST + kk    ], phi[mt][1], plo[mt][1]);
                split2(Ps[(rb    ) * PST + kk + 4], phi[mt][2], plo[mt][2]);
                split2(Ps[(rb + 8) * PST + kk + 4], phi[mt][3], plo[mt][3]);
            }
            uint32_t vhi[8][2], vlo[8][2];
            #pragma unroll
            for (int nt = 0; nt < 8; nt++) {
                int dd = nt * 8 + g;
                split2(Vs[(kk    ) * VST + dd], vhi[nt][0], vlo[nt][0]);
                split2(Vs[(kk + 4) * VST + dd], vhi[nt][1], vlo[nt][1]);
            }
            #pragma unroll
            for (int mt = 0; mt < 2; mt++)
                #pragma unroll
                for (int nt = 0; nt < 8; nt++) {
                    mma8(acc[mt][nt], phi[mt], vhi[nt]);
                    mma8(acc[mt][nt], plo[mt], vhi[nt]);
                    mma8(acc[mt][nt], phi[mt], vlo[nt]);
                }
        }
        __syncthreads();   // protect K/V/mask overwrite next iter
    }

    // ---- epilogue ----
    #pragma unroll
    for (int mt = 0; mt < 2; mt++) {
        int rb = q0 + w * 32 + mt * 16 + g;
        float inv0 = 1.f / li[mt * 2], inv1 = 1.f / li[mt * 2 + 1];
        #pragma unroll
        for (int nt = 0; nt < 8; nt++) {
            int col = h * 64 + nt * 8 + 2 * cq;
            *(float2*)&g_ao[((size_t)(n * SEQ + rb    )) * EMB + col] =
                make_float2(acc[mt][nt][0] * inv0, acc[mt][nt][1] * inv0);
            *(float2*)&g_ao[((size_t)(n * SEQ + rb + 8)) * EMB + col] =
                make_float2(acc[mt][nt][2] * inv1, acc[mt][nt][3] * inv1);
        }
    }
}

// ============================================================
extern "C" void kernel_launch(void* const* d_in, const int* in_sizes, int n_in,
                              void* d_out, int out_size)
{
    const float* values = (const float*)d_in[0];
    const float* keys   = (const float*)d_in[1];
    const float* query  = (const float*)d_in[2];
    const int*   mask   = (const int*)  d_in[3];
    const float* Wv     = (const float*)d_in[4];
    const float* Wk     = (const float*)d_in[5];
    const float* Wq     = (const float*)d_in[6];
    const float* Wo     = (const float*)d_in[7];
    const float* bo     = (const float*)d_in[8];

    // 1) projections (q,k,v head-split)
    dim3 gproj(EMB / 128, NROWS / 128, 3);
    proj_kernel<<<gproj, 256>>>(values, keys, query, Wv, Wk, Wq);

    // 2) flash attention (3xTF32 mma)
    size_t smem = (size_t)(BQF * QST + BKV * QST + BKV * VST + BQF * PST) * sizeof(float)
                + BKV * sizeof(int);
    cudaFuncSetAttribute(flash_kernel, cudaFuncAttributeMaxDynamicSharedMemorySize, (int)smem);
    flash_kernel<<<dim3(SEQ / BQF, N_B * H), 256, smem>>>(mask);

    // 3) output projection + bias
    out_kernel<<<dim3(EMB / 128, NROWS / 128), 256>>>(Wo, bo, (float*)d_out);
}

// round 3
// speedup vs baseline: 1.4824x; 1.1901x over previous
#include <cuda_runtime.h>
#include <stdint.h>

#define N_B   8
#define SEQ   2048
#define EMB   512
#define H     8
#define HD    64
#define NROWS (N_B*SEQ)
#define HSZ   ((size_t)N_B*H*SEQ*HD)

// -------- scratch (no cudaMalloc allowed) --------
__device__ float g_whi[4*EMB*EMB], g_wlo[4*EMB*EMB];
__device__ float g_qhi[HSZ], g_qlo[HSZ];
__device__ float g_khi[HSZ], g_klo[HSZ];
__device__ float g_vhi[HSZ], g_vlo[HSZ];
__device__ float g_ao[(size_t)NROWS*EMB];

// ---------------- helpers ----------------
__device__ __forceinline__ uint32_t f2tf(float x) {
    uint32_t r; asm("cvt.rna.tf32.f32 %0, %1;" : "=r"(r) : "f"(x)); return r;
}
__device__ __forceinline__ void split2(float x, uint32_t &hi, uint32_t &lo) {
    hi = f2tf(x);
    lo = f2tf(x - __uint_as_float(hi));
}
__device__ __forceinline__ void mma8(float c[4], const uint32_t a[4], const uint32_t b[2]) {
    asm volatile(
      "mma.sync.aligned.m16n8k8.row.col.f32.tf32.tf32.f32 "
      "{%0,%1,%2,%3},{%4,%5,%6,%7},{%8,%9},{%0,%1,%2,%3};\n"
      : "+f"(c[0]), "+f"(c[1]), "+f"(c[2]), "+f"(c[3])
      : "r"(a[0]), "r"(a[1]), "r"(a[2]), "r"(a[3]), "r"(b[0]), "r"(b[1]));
}
__device__ __forceinline__ void cpa16(void* s, const void* g) {
    uint32_t sa = (uint32_t)__cvta_generic_to_shared(s);
    asm volatile("cp.async.cg.shared.global [%0], [%1], 16;" :: "r"(sa), "l"(g) : "memory");
}
#define CPCOMMIT() asm volatile("cp.async.commit_group;" ::: "memory")
#define CPWAIT(n)  asm volatile("cp.async.wait_group %0;" :: "n"(n) : "memory")

// ============================================================
// Pre-split weights: Wv,Wk,Wq,Wo -> g_whi/g_wlo slots 0..3
// ============================================================
__global__ __launch_bounds__(256) void split_w(
    const float* __restrict__ Wv, const float* __restrict__ Wk,
    const float* __restrict__ Wq, const float* __restrict__ Wo)
{
    const int slot = blockIdx.y;
    const float* src = (slot==0)?Wv:(slot==1)?Wk:(slot==2)?Wq:Wo;
    int i = blockIdx.x * 256 + threadIdx.x;
    float x = src[i];
    uint32_t hi, lo; split2(x, hi, lo);
    g_whi[(size_t)slot*EMB*EMB + i] = __uint_as_float(hi);
    g_wlo[(size_t)slot*EMB*EMB + i] = __uint_as_float(lo);
}

// ============================================================
// Double-buffered 3xTF32 GEMM core. C[128x128] = X @ W.
// X raw fp32 (split inline, once), W pre-split hi/lo.
// 8 warps: 4(m) x 2(n), warp tile 32x64.
// ============================================================
#define AST 36
#define BST 136
#define GEMM_SMEM ((2*128*AST + 2*2*32*BST) * 4)

__device__ __forceinline__ void gemm_prefetch(
    const float* __restrict__ X, const float* __restrict__ Whi,
    const float* __restrict__ Wlo, float (*As)[AST], float (*Bh)[BST],
    float (*Bl)[BST], int m0, int n0, int k0, int buf, int tid)
{
    #pragma unroll
    for (int it = 0; it < 4; it++) {
        int f = tid + 256 * it;
        int row = f >> 3, c4 = f & 7;
        cpa16(&As[buf*128 + row][c4*4], X + (size_t)(m0+row)*EMB + k0 + c4*4);
    }
    #pragma unroll
    for (int it = 0; it < 4; it++) {
        int f = tid + 256 * it;
        int row = f >> 5, c4 = f & 31;
        cpa16(&Bh[buf*32 + row][c4*4], Whi + (size_t)(k0+row)*EMB + n0 + c4*4);
        cpa16(&Bl[buf*32 + row][c4*4], Wlo + (size_t)(k0+row)*EMB + n0 + c4*4);
    }
}

__device__ __forceinline__ void gemm_core(
    const float* __restrict__ X, const float* __restrict__ Whi,
    const float* __restrict__ Wlo, float* sm, float c[2][8][4],
    int m0, int n0, int tid)
{
    float (*As)[AST] = reinterpret_cast<float(*)[AST]>(sm);
    float (*Bh)[BST] = reinterpret_cast<float(*)[BST]>(sm + 2*128*AST);
    float (*Bl)[BST] = reinterpret_cast<float(*)[BST]>(sm + 2*128*AST + 2*32*BST);

    const int lane = tid & 31, w = tid >> 5;
    const int g = lane >> 2, cq = lane & 3;
    const int wm = (w & 3) * 32, wn = (w >> 2) * 64;

    #pragma unroll
    for (int mt = 0; mt < 2; mt++)
        #pragma unroll
        for (int nt = 0; nt < 8; nt++)
            #pragma unroll
            for (int e = 0; e < 4; e++) c[mt][nt][e] = 0.f;

    gemm_prefetch(X, Whi, Wlo, As, Bh, Bl, m0, n0, 0, 0, tid);
    CPCOMMIT();

    for (int t = 0; t < 16; t++) {
        if (t < 15) {
            gemm_prefetch(X, Whi, Wlo, As, Bh, Bl, m0, n0, (t+1)*32, (t+1)&1, tid);
            CPCOMMIT();
            CPWAIT(1);
        } else {
            CPWAIT(0);
        }
        __syncthreads();

        const int ab = (t & 1) * 128, bb = (t & 1) * 32;
        #pragma unroll
        for (int ks = 0; ks < 4; ks++) {
            const int kk = ks * 8 + cq;
            uint32_t ahi[2][4], alo[2][4];
            #pragma unroll
            for (int mt = 0; mt < 2; mt++) {
                int rb = ab + wm + mt*16 + g;
                split2(As[rb    ][kk    ], ahi[mt][0], alo[mt][0]);
                split2(As[rb + 8][kk    ], ahi[mt][1], alo[mt][1]);
                split2(As[rb    ][kk + 4], ahi[mt][2], alo[mt][2]);
                split2(As[rb + 8][kk + 4], ahi[mt][3], alo[mt][3]);
            }
            uint32_t bhi[8][2], blo[8][2];
            #pragma unroll
            for (int nt = 0; nt < 8; nt++) {
                int nn = wn + nt*8 + g;
                bhi[nt][0] = __float_as_uint(Bh[bb+kk  ][nn]);
                bhi[nt][1] = __float_as_uint(Bh[bb+kk+4][nn]);
                blo[nt][0] = __float_as_uint(Bl[bb+kk  ][nn]);
                blo[nt][1] = __float_as_uint(Bl[bb+kk+4][nn]);
            }
            #pragma unroll
            for (int mt = 0; mt < 2; mt++)
                #pragma unroll
                for (int nt = 0; nt < 8; nt++) {
                    mma8(c[mt][nt], ahi[mt], bhi[nt]);
                    mma8(c[mt][nt], alo[mt], bhi[nt]);
                    mma8(c[mt][nt], ahi[mt], blo[nt]);
                }
        }
        __syncthreads();
    }
}

// ============================================================
// Projections: head-split epilogue writing pre-split hi/lo.
// Q additionally folded with 1/sqrt(HD)=0.125.
// ============================================================
__global__ __launch_bounds__(256, 1) void proj_kernel(
    const float* __restrict__ values, const float* __restrict__ keys,
    const float* __restrict__ query)
{
    extern __shared__ float sm[];
    const int which = blockIdx.z;   // 0:v 1:k 2:q (matches W slots)
    const float* X = (which == 0) ? values : (which == 1) ? keys : query;
    const float* Whi = g_whi + (size_t)which * EMB * EMB;
    const float* Wlo = g_wlo + (size_t)which * EMB * EMB;
    float* dhi = (which == 0) ? g_vhi : (which == 1) ? g_khi : g_qhi;
    float* dlo = (which == 0) ? g_vlo : (which == 1) ? g_klo : g_qlo;
    const float post = (which == 2) ? 0.125f : 1.0f;

    const int m0 = blockIdx.y * 128, n0 = blockIdx.x * 128;
    float c[2][8][4];
    gemm_core(X, Whi, Wlo, sm, c, m0, n0, threadIdx.x);

    const int lane = threadIdx.x & 31, w = threadIdx.x >> 5;
    const int g = lane >> 2, cq = lane & 3;
    const int wm = (w & 3) * 32, wn = (w >> 2) * 64;

    #pragma unroll
    for (int mt = 0; mt < 2; mt++) {
        #pragma unroll
        for (int half = 0; half < 2; half++) {
            int row = m0 + wm + mt*16 + g + half*8;
            int n = row >> 11, s = row & 2047;
            #pragma unroll
            for (int nt = 0; nt < 8; nt++) {
                int col = n0 + wn + nt*8 + 2*cq;
                int h = col >> 6, d = col & 63;
                size_t base = (((size_t)(n * H + h)) * SEQ + s) * HD + d;
                uint32_t h0, l0, h1, l1;
                split2(c[mt][nt][half*2+0] * post, h0, l0);
                split2(c[mt][nt][half*2+1] * post, h1, l1);
                *(float2*)&dhi[base] = make_float2(__uint_as_float(h0), __uint_as_float(h1));
                *(float2*)&dlo[base] = make_float2(__uint_as_float(l0), __uint_as_float(l1));
            }
        }
    }
}

// ============================================================
// Output GEMM: out = g_ao @ Wo + bo
// ============================================================
__global__ __launch_bounds__(256, 1) void out_kernel(
    const float* __restrict__ bo, float* __restrict__ out)
{
    extern __shared__ float sm[];
    const int m0 = blockIdx.y * 128, n0 = blockIdx.x * 128;
    float c[2][8][4];
    gemm_core(g_ao, g_whi + (size_t)3*EMB*EMB, g_wlo + (size_t)3*EMB*EMB,
              sm, c, m0, n0, threadIdx.x);

    const int lane = threadIdx.x & 31, w = threadIdx.x >> 5;
    const int g = lane >> 2, cq = lane & 3;
    const int wm = (w & 3) * 32, wn = (w >> 2) * 64;

    #pragma unroll
    for (int mt = 0; mt < 2; mt++) {
        #pragma unroll
        for (int half = 0; half < 2; half++) {
            size_t row = m0 + wm + mt*16 + g + half*8;
            #pragma unroll
            for (int nt = 0; nt < 8; nt++) {
                int col = n0 + wn + nt*8 + 2*cq;
                float2 v = make_float2(c[mt][nt][half*2+0] + bo[col],
                                       c[mt][nt][half*2+1] + bo[col+1]);
                *(float2*)&out[row * EMB + col] = v;
            }
        }
    }
}

// ============================================================
// Flash attention, 3xTF32, pre-split Q/K/V.
// BQ=128, BKV=64. 8 warps; warp w owns q-rows [w*16, w*16+16).
// ============================================================
#define BQF 128
#define BKV 64
#define QSTf 68
#define VSTf 72
#define PSTf 76
#define FLASH_SMEM ((2*BQF*QSTf + 2*BKV*QSTf + 2*BKV*VSTf + BQF*PSTf)*4 + BKV*4)

__global__ __launch_bounds__(256, 1) void flash_kernel(const int* __restrict__ mask)
{
    extern __shared__ float sm[];
    float* Qh = sm;
    float* Ql = Qh + BQF * QSTf;
    float* Kh = Ql + BQF * QSTf;
    float* Kl = Kh + BKV * QSTf;
    float* Vh = Kl + BKV * QSTf;
    float* Vl = Vh + BKV * VSTf;
    float* Ps = Vl + BKV * VSTf;
    int*   ms = (int*)(Ps + BQF * PSTf);

    const int tid = threadIdx.x;
    const int lane = tid & 31, w = tid >> 5;
    const int g = lane >> 2, cq = lane & 3;
    const int q0 = blockIdx.x * BQF;
    const int nh = blockIdx.y;
    const int n = nh >> 3, h = nh & 7;
    const float* Qhg = g_qhi + (size_t)nh * SEQ * HD;
    const float* Qlg = g_qlo + (size_t)nh * SEQ * HD;
    const float* Khg = g_khi + (size_t)nh * SEQ * HD;
    const float* Klg = g_klo + (size_t)nh * SEQ * HD;
    const float* Vhg = g_vhi + (size_t)nh * SEQ * HD;
    const float* Vlg = g_vlo + (size_t)nh * SEQ * HD;
    const int* mrow = mask + n * SEQ;

    // load Q (pre-split, pre-scaled)
    #pragma unroll
    for (int it = 0; it < 8; it++) {
        int f = tid + 256 * it;
        int row = f >> 4, c4 = f & 15;
        cpa16(&Qh[row*QSTf + c4*4], Qhg + (size_t)(q0+row)*HD + c4*4);
        cpa16(&Ql[row*QSTf + c4*4], Qlg + (size_t)(q0+row)*HD + c4*4);
    }
    CPCOMMIT();

    float acc[8][4];
    float mi[2] = {-1e30f, -1e30f}, li[2] = {0.f, 0.f};
    #pragma unroll
    for (int nt = 0; nt < 8; nt++)
        #pragma unroll
        for (int e = 0; e < 4; e++) acc[nt][e] = 0.f;

    const int rb = w * 16 + g;

    for (int k0 = 0; k0 < SEQ; k0 += BKV) {
        // load K,V tiles + mask
        #pragma unroll
        for (int it = 0; it < 4; it++) {
            int f = tid + 256 * it;
            int row = f >> 4, c4 = f & 15;
            size_t go = (size_t)(k0 + row) * HD + c4 * 4;
            cpa16(&Kh[row*QSTf + c4*4], Khg + go);
            cpa16(&Kl[row*QSTf + c4*4], Klg + go);
            cpa16(&Vh[row*VSTf + c4*4], Vhg + go);
            cpa16(&Vl[row*VSTf + c4*4], Vlg + go);
        }
        if (tid < 16) cpa16(&ms[tid*4], mrow + k0 + tid*4);
        CPCOMMIT(); CPWAIT(0);
        __syncthreads();

        // ---- S = Q @ K^T ----
        float s[8][4];
        #pragma unroll
        for (int nt = 0; nt < 8; nt++)
            #pragma unroll
            for (int e = 0; e < 4; e++) s[nt][e] = 0.f;

        #pragma unroll
        for (int ks = 0; ks < 8; ks++) {
            const int kk = ks * 8 + cq;
            uint32_t ah[4], al[4];
            ah[0] = __float_as_uint(Qh[(rb  )*QSTf + kk  ]);
            ah[1] = __float_as_uint(Qh[(rb+8)*QSTf + kk  ]);
            ah[2] = __float_as_uint(Qh[(rb  )*QSTf + kk+4]);
            ah[3] = __float_as_uint(Qh[(rb+8)*QSTf + kk+4]);
            al[0] = __float_as_uint(Ql[(rb  )*QSTf + kk  ]);
            al[1] = __float_as_uint(Ql[(rb+8)*QSTf + kk  ]);
            al[2] = __float_as_uint(Ql[(rb  )*QSTf + kk+4]);
            al[3] = __float_as_uint(Ql[(rb+8)*QSTf + kk+4]);
            uint32_t bh[8][2], bl[8][2];
            #pragma unroll
            for (int nt = 0; nt < 8; nt++) {
                int nn = nt * 8 + g;
                bh[nt][0] = __float_as_uint(Kh[nn*QSTf + kk  ]);
                bh[nt][1] = __float_as_uint(Kh[nn*QSTf + kk+4]);
                bl[nt][0] = __float_as_uint(Kl[nn*QSTf + kk  ]);
                bl[nt][1] = __float_as_uint(Kl[nn*QSTf + kk+4]);
            }
            #pragma unroll
            for (int nt = 0; nt < 8; nt++) {
                mma8(s[nt], ah, bh[nt]);
                mma8(s[nt], al, bh[nt]);
                mma8(s[nt], ah, bl[nt]);
            }
        }

        // ---- mask + online softmax (scale pre-folded into Q) ----
        float mx0 = -1e30f, mx1 = -1e30f;
        #pragma unroll
        for (int nt = 0; nt < 8; nt++) {
            #pragma unroll
            for (int j = 0; j < 2; j++) {
                int mv = ms[nt*8 + 2*cq + j];
                float v0 = mv ? s[nt][j]   : -1e30f;
                float v1 = mv ? s[nt][2+j] : -1e30f;
                s[nt][j] = v0; s[nt][2+j] = v1;
                mx0 = fmaxf(mx0, v0); mx1 = fmaxf(mx1, v1);
            }
        }
        mx0 = fmaxf(mx0, __shfl_xor_sync(0xffffffffu, mx0, 1));
        mx0 = fmaxf(mx0, __shfl_xor_sync(0xffffffffu, mx0, 2));
        mx1 = fmaxf(mx1, __shfl_xor_sync(0xffffffffu, mx1, 1));
        mx1 = fmaxf(mx1, __shfl_xor_sync(0xffffffffu, mx1, 2));

        float mn0 = fmaxf(mi[0], mx0), mn1 = fmaxf(mi[1], mx1);
        float cr0 = __expf(mi[0] - mn0), cr1 = __expf(mi[1] - mn1);
        float sum0 = 0.f, sum1 = 0.f;
        #pragma unroll
        for (int nt = 0; nt < 8; nt++) {
            float p0 = __expf(s[nt][0] - mn0);
            float p1 = __expf(s[nt][1] - mn0);
            float p2 = __expf(s[nt][2] - mn1);
            float p3 = __expf(s[nt][3] - mn1);
            sum0 += p0 + p1; sum1 += p2 + p3;
            *(float2*)&Ps[(rb  )*PSTf + nt*8 + 2*cq] = make_float2(p0, p1);
            *(float2*)&Ps[(rb+8)*PSTf + nt*8 + 2*cq] = make_float2(p2, p3);
            acc[nt][0] *= cr0; acc[nt][1] *= cr0;
            acc[nt][2] *= cr1; acc[nt][3] *= cr1;
        }
        sum0 += __shfl_xor_sync(0xffffffffu, sum0, 1);
        sum0 += __shfl_xor_sync(0xffffffffu, sum0, 2);
        sum1 += __shfl_xor_sync(0xffffffffu, sum1, 1);
        sum1 += __shfl_xor_sync(0xffffffffu, sum1, 2);
        li[0] = li[0] * cr0 + sum0; mi[0] = mn0;
        li[1] = li[1] * cr1 + sum1; mi[1] = mn1;
        __syncwarp();   // P tile is warp-local

        // ---- O += P @ V ----
        #pragma unroll
        for (int ks = 0; ks < 8; ks++) {
            const int kk = ks * 8 + cq;
            uint32_t ph[4], pl[4];
            split2(Ps[(rb  )*PSTf + kk  ], ph[0], pl[0]);
            split2(Ps[(rb+8)*PSTf + kk  ], ph[1], pl[1]);
            split2(Ps[(rb  )*PSTf + kk+4], ph[2], pl[2]);
            split2(Ps[(rb+8)*PSTf + kk+4], ph[3], pl[3]);
            uint32_t vh[8][2], vl[8][2];
            #pragma unroll
            for (int nt = 0; nt < 8; nt++) {
                int dd = nt * 8 + g;
                vh[nt][0] = __float_as_uint(Vh[(kk  )*VSTf + dd]);
                vh[nt][1] = __float_as_uint(Vh[(kk+4)*VSTf + dd]);
                vl[nt][0] = __float_as_uint(Vl[(kk  )*VSTf + dd]);
                vl[nt][1] = __float_as_uint(Vl[(kk+4)*VSTf + dd]);
            }
            #pragma unroll
            for (int nt = 0; nt < 8; nt++) {
                mma8(acc[nt], ph, vh[nt]);
                mma8(acc[nt], pl, vh[nt]);
                mma8(acc[nt], ph, vl[nt]);
            }
        }
        __syncthreads();   // protect K/V/mask for next iter
    }

    // ---- epilogue ----
    float inv0 = 1.f / li[0], inv1 = 1.f / li[1];
    #pragma unroll
    for (int nt = 0; nt < 8; nt++) {
        int col = h * 64 + nt * 8 + 2 * cq;
        size_t r0 = (size_t)(n * SEQ + q0 + rb) * EMB + col;
        size_t r1 = (size_t)(n * SEQ + q0 + rb + 8) * EMB + col;
        *(float2*)&g_ao[r0] = make_float2(acc[nt][0]*inv0, acc[nt][1]*inv0);
        *(float2*)&g_ao[r1] = make_float2(acc[nt][2]*inv1, acc[nt][3]*inv1);
    }
}

// ============================================================
extern "C" void kernel_launch(void* const* d_in, const int* in_sizes, int n_in,
                              void* d_out, int out_size)
{
    const float* values = (const float*)d_in[0];
    const float* keys   = (const float*)d_in[1];
    const float* query  = (const float*)d_in[2];
    const int*   mask   = (const int*)  d_in[3];
    const float* Wv     = (const float*)d_in[4];
    const float* Wk     = (const float*)d_in[5];
    const float* Wq     = (const float*)d_in[6];
    const float* Wo     = (const float*)d_in[7];
    const float* bo     = (const float*)d_in[8];

    // 0) pre-split weights
    split_w<<<dim3(EMB*EMB/256, 4), 256>>>(Wv, Wk, Wq, Wo);

    // 1) projections (write pre-split head-split q,k,v)
    cudaFuncSetAttribute(proj_kernel, cudaFuncAttributeMaxDynamicSharedMemorySize, GEMM_SMEM);
    proj_kernel<<<dim3(EMB/128, NROWS/128, 3), 256, GEMM_SMEM>>>(values, keys, query);

    // 2) flash attention
    cudaFuncSetAttribute(flash_kernel, cudaFuncAttributeMaxDynamicSharedMemorySize, FLASH_SMEM);
    flash_kernel<<<dim3(SEQ/BQF, N_B*H), 256, FLASH_SMEM>>>(mask);

    // 3) output projection + bias
    cudaFuncSetAttribute(out_kernel, cudaFuncAttributeMaxDynamicSharedMemorySize, GEMM_SMEM);
    out_kernel<<<dim3(EMB/128, NROWS/128), 256, GEMM_SMEM>>>(bo, (float*)d_out);
}

// round 4
// speedup vs baseline: 1.6307x; 1.1001x over previous
#include <cuda_runtime.h>
#include <stdint.h>

#define N_B   8
#define SEQ   2048
#define EMB   512
#define H     8
#define HD    64
#define NROWS (N_B*SEQ)
#define HSZ   ((size_t)N_B*H*SEQ*HD)

// -------- scratch (no cudaMalloc allowed) --------
__device__ float g_whi[4*EMB*EMB], g_wlo[4*EMB*EMB];
__device__ float g_qs [HSZ];                  // raw fp32, pre-scaled by 0.125
__device__ float g_khi[HSZ], g_klo[HSZ];
__device__ float g_vhi[HSZ], g_vlo[HSZ];
__device__ float g_ao[(size_t)NROWS*EMB];

// ---------------- helpers ----------------
__device__ __forceinline__ uint32_t f2tf(float x) {
    uint32_t r; asm("cvt.rna.tf32.f32 %0, %1;" : "=r"(r) : "f"(x)); return r;
}
__device__ __forceinline__ void split2(float x, uint32_t &hi, uint32_t &lo) {
    hi = f2tf(x);
    lo = f2tf(x - __uint_as_float(hi));
}
__device__ __forceinline__ void mma8(float c[4], const uint32_t a[4], const uint32_t b[2]) {
    asm volatile(
      "mma.sync.aligned.m16n8k8.row.col.f32.tf32.tf32.f32 "
      "{%0,%1,%2,%3},{%4,%5,%6,%7},{%8,%9},{%0,%1,%2,%3};\n"
      : "+f"(c[0]), "+f"(c[1]), "+f"(c[2]), "+f"(c[3])
      : "r"(a[0]), "r"(a[1]), "r"(a[2]), "r"(a[3]), "r"(b[0]), "r"(b[1]));
}
__device__ __forceinline__ void cpa16(void* s, const void* g) {
    uint32_t sa = (uint32_t)__cvta_generic_to_shared(s);
    asm volatile("cp.async.cg.shared.global [%0], [%1], 16;" :: "r"(sa), "l"(g) : "memory");
}
#define CPCOMMIT() asm volatile("cp.async.commit_group;" ::: "memory")
#define CPWAIT(n)  asm volatile("cp.async.wait_group %0;" :: "n"(n) : "memory")

// ============================================================
// Pre-split weights: Wv,Wk,Wq,Wo -> g_whi/g_wlo slots 0..3
// ============================================================
__global__ __launch_bounds__(256) void split_w(
    const float* __restrict__ Wv, const float* __restrict__ Wk,
    const float* __restrict__ Wq, const float* __restrict__ Wo)
{
    const int slot = blockIdx.y;
    const float* src = (slot==0)?Wv:(slot==1)?Wk:(slot==2)?Wq:Wo;
    int i = blockIdx.x * 256 + threadIdx.x;
    float x = src[i];
    uint32_t hi, lo; split2(x, hi, lo);
    g_whi[(size_t)slot*EMB*EMB + i] = __uint_as_float(hi);
    g_wlo[(size_t)slot*EMB*EMB + i] = __uint_as_float(lo);
}

// ============================================================
// Double-buffered 3xTF32 GEMM core, 2 CTAs/SM.
// ============================================================
#define AST 36
#define BST 136
#define GEMM_SMEM ((2*128*AST + 2*2*32*BST) * 4)

__device__ __forceinline__ void gemm_prefetch(
    const float* __restrict__ X, const float* __restrict__ Whi,
    const float* __restrict__ Wlo, float (*As)[AST], float (*Bh)[BST],
    float (*Bl)[BST], int m0, int n0, int k0, int buf, int tid)
{
    #pragma unroll
    for (int it = 0; it < 4; it++) {
        int f = tid + 256 * it;
        int row = f >> 3, c4 = f & 7;
        cpa16(&As[buf*128 + row][c4*4], X + (size_t)(m0+row)*EMB + k0 + c4*4);
    }
    #pragma unroll
    for (int it = 0; it < 4; it++) {
        int f = tid + 256 * it;
        int row = f >> 5, c4 = f & 31;
        cpa16(&Bh[buf*32 + row][c4*4], Whi + (size_t)(k0+row)*EMB + n0 + c4*4);
        cpa16(&Bl[buf*32 + row][c4*4], Wlo + (size_t)(k0+row)*EMB + n0 + c4*4);
    }
}

__device__ __forceinline__ void gemm_core(
    const float* __restrict__ X, const float* __restrict__ Whi,
    const float* __restrict__ Wlo, float* sm, float c[2][8][4],
    int m0, int n0, int tid)
{
    float (*As)[AST] = reinterpret_cast<float(*)[AST]>(sm);
    float (*Bh)[BST] = reinterpret_cast<float(*)[BST]>(sm + 2*128*AST);
    float (*Bl)[BST] = reinterpret_cast<float(*)[BST]>(sm + 2*128*AST + 2*32*BST);

    const int lane = tid & 31, w = tid >> 5;
    const int g = lane >> 2, cq = lane & 3;
    const int wm = (w & 3) * 32, wn = (w >> 2) * 64;

    #pragma unroll
    for (int mt = 0; mt < 2; mt++)
        #pragma unroll
        for (int nt = 0; nt < 8; nt++)
            #pragma unroll
            for (int e = 0; e < 4; e++) c[mt][nt][e] = 0.f;

    gemm_prefetch(X, Whi, Wlo, As, Bh, Bl, m0, n0, 0, 0, tid);
    CPCOMMIT();

    for (int t = 0; t < 16; t++) {
        if (t < 15) {
            gemm_prefetch(X, Whi, Wlo, As, Bh, Bl, m0, n0, (t+1)*32, (t+1)&1, tid);
            CPCOMMIT();
            CPWAIT(1);
        } else {
            CPWAIT(0);
        }
        __syncthreads();

        const int ab = (t & 1) * 128, bb = (t & 1) * 32;
        #pragma unroll
        for (int ks = 0; ks < 4; ks++) {
            const int kk = ks * 8 + cq;
            uint32_t ahi[2][4], alo[2][4];
            #pragma unroll
            for (int mt = 0; mt < 2; mt++) {
                int rb = ab + wm + mt*16 + g;
                split2(As[rb    ][kk    ], ahi[mt][0], alo[mt][0]);
                split2(As[rb + 8][kk    ], ahi[mt][1], alo[mt][1]);
                split2(As[rb    ][kk + 4], ahi[mt][2], alo[mt][2]);
                split2(As[rb + 8][kk + 4], ahi[mt][3], alo[mt][3]);
            }
            uint32_t bhi[8][2], blo[8][2];
            #pragma unroll
            for (int nt = 0; nt < 8; nt++) {
                int nn = wn + nt*8 + g;
                bhi[nt][0] = __float_as_uint(Bh[bb+kk  ][nn]);
                bhi[nt][1] = __float_as_uint(Bh[bb+kk+4][nn]);
                blo[nt][0] = __float_as_uint(Bl[bb+kk  ][nn]);
                blo[nt][1] = __float_as_uint(Bl[bb+kk+4][nn]);
            }
            #pragma unroll
            for (int mt = 0; mt < 2; mt++)
                #pragma unroll
                for (int nt = 0; nt < 8; nt++) {
                    mma8(c[mt][nt], ahi[mt], bhi[nt]);
                    mma8(c[mt][nt], alo[mt], bhi[nt]);
                    mma8(c[mt][nt], ahi[mt], blo[nt]);
                }
        }
        __syncthreads();
    }
}

// ============================================================
// Projections: K/V written pre-split hi/lo; Q written raw*0.125
// ============================================================
__global__ __launch_bounds__(256, 2) void proj_kernel(
    const float* __restrict__ values, const float* __restrict__ keys,
    const float* __restrict__ query)
{
    extern __shared__ float sm[];
    const int which = blockIdx.z;   // 0:v 1:k 2:q
    const float* X = (which == 0) ? values : (which == 1) ? keys : query;
    const float* Whi = g_whi + (size_t)which * EMB * EMB;
    const float* Wlo = g_wlo + (size_t)which * EMB * EMB;

    const int m0 = blockIdx.y * 128, n0 = blockIdx.x * 128;
    float c[2][8][4];
    gemm_core(X, Whi, Wlo, sm, c, m0, n0, threadIdx.x);

    const int lane = threadIdx.x & 31, w = threadIdx.x >> 5;
    const int g = lane >> 2, cq = lane & 3;
    const int wm = (w & 3) * 32, wn = (w >> 2) * 64;

    if (which == 2) {
        #pragma unroll
        for (int mt = 0; mt < 2; mt++)
            #pragma unroll
            for (int half = 0; half < 2; half++) {
                int row = m0 + wm + mt*16 + g + half*8;
                int n = row >> 11, s = row & 2047;
                #pragma unroll
                for (int nt = 0; nt < 8; nt++) {
                    int col = n0 + wn + nt*8 + 2*cq;
                    int h = col >> 6, d = col & 63;
                    size_t base = (((size_t)(n * H + h)) * SEQ + s) * HD + d;
                    *(float2*)&g_qs[base] = make_float2(
                        c[mt][nt][half*2+0] * 0.125f, c[mt][nt][half*2+1] * 0.125f);
                }
            }
    } else {
        float* dhi = (which == 0) ? g_vhi : g_khi;
        float* dlo = (which == 0) ? g_vlo : g_klo;
        #pragma unroll
        for (int mt = 0; mt < 2; mt++)
            #pragma unroll
            for (int half = 0; half < 2; half++) {
                int row = m0 + wm + mt*16 + g + half*8;
                int n = row >> 11, s = row & 2047;
                #pragma unroll
                for (int nt = 0; nt < 8; nt++) {
                    int col = n0 + wn + nt*8 + 2*cq;
                    int h = col >> 6, d = col & 63;
                    size_t base = (((size_t)(n * H + h)) * SEQ + s) * HD + d;
                    uint32_t h0, l0, h1, l1;
                    split2(c[mt][nt][half*2+0], h0, l0);
                    split2(c[mt][nt][half*2+1], h1, l1);
                    *(float2*)&dhi[base] = make_float2(__uint_as_float(h0), __uint_as_float(h1));
                    *(float2*)&dlo[base] = make_float2(__uint_as_float(l0), __uint_as_float(l1));
                }
            }
    }
}

// ============================================================
// Output GEMM: out = g_ao @ Wo + bo
// ============================================================
__global__ __launch_bounds__(256, 2) void out_kernel(
    const float* __restrict__ bo, float* __restrict__ out)
{
    extern __shared__ float sm[];
    const int m0 = blockIdx.y * 128, n0 = blockIdx.x * 128;
    float c[2][8][4];
    gemm_core(g_ao, g_whi + (size_t)3*EMB*EMB, g_wlo + (size_t)3*EMB*EMB,
              sm, c, m0, n0, threadIdx.x);

    const int lane = threadIdx.x & 31, w = threadIdx.x >> 5;
    const int g = lane >> 2, cq = lane & 3;
    const int wm = (w & 3) * 32, wn = (w >> 2) * 64;

    #pragma unroll
    for (int mt = 0; mt < 2; mt++)
        #pragma unroll
        for (int half = 0; half < 2; half++) {
            size_t row = m0 + wm + mt*16 + g + half*8;
            #pragma unroll
            for (int nt = 0; nt < 8; nt++) {
                int col = n0 + wn + nt*8 + 2*cq;
                float2 v = make_float2(c[mt][nt][half*2+0] + bo[col],
                                       c[mt][nt][half*2+1] + bo[col+1]);
                *(float2*)&out[row * EMB + col] = v;
            }
        }
}

// ============================================================
// Flash attention: Q frags in registers, K/V double-buffered.
// BQ=128, BKV=64, 8 warps, warp w owns q-rows [w*16, w*16+16).
// ============================================================
#define BQF 128
#define BKV 64
#define KST 68
#define VST 72
#define PST 76
// smem floats: Kh 2*64*68, Kl same, Vh 2*64*72, Vl same, Ps 128*76, ms 2*64 ints
#define FL_KH 0
#define FL_KL (FL_KH + 2*BKV*KST)
#define FL_VH (FL_KL + 2*BKV*KST)
#define FL_VL (FL_VH + 2*BKV*VST)
#define FL_PS (FL_VL + 2*BKV*VST)
#define FL_MS (FL_PS + BQF*PST)
#define FLASH_SMEM ((FL_MS + 2*BKV) * 4)

__global__ __launch_bounds__(256, 1) void flash_kernel(const int* __restrict__ mask)
{
    extern __shared__ float sm[];
    float* Kh = sm + FL_KH;
    float* Kl = sm + FL_KL;
    float* Vh = sm + FL_VH;
    float* Vl = sm + FL_VL;
    float* Ps = sm + FL_PS;
    int*   ms = (int*)(sm + FL_MS);

    const int tid = threadIdx.x;
    const int lane = tid & 31, w = tid >> 5;
    const int g = lane >> 2, cq = lane & 3;
    const int q0 = blockIdx.x * BQF;
    const int nh = blockIdx.y;
    const int n = nh >> 3, h = nh & 7;
    const float* Qg  = g_qs  + (size_t)nh * SEQ * HD;
    const float* Khg = g_khi + (size_t)nh * SEQ * HD;
    const float* Klg = g_klo + (size_t)nh * SEQ * HD;
    const float* Vhg = g_vhi + (size_t)nh * SEQ * HD;
    const float* Vlg = g_vlo + (size_t)nh * SEQ * HD;
    const int* mrow = mask + n * SEQ;
    const int rb = w * 16 + g;

    // ---- stage Q through Ps, split into registers ----
    #pragma unroll
    for (int it = 0; it < 8; it++) {
        int f = tid + 256 * it;
        int row = f >> 4, c4 = f & 15;
        cpa16(&Ps[row*PST + c4*4], Qg + (size_t)(q0+row)*HD + c4*4);
    }
    CPCOMMIT();

    // ---- prefetch k-tile 0 ----
    {
        #pragma unroll
        for (int it = 0; it < 4; it++) {
            int f = tid + 256 * it;
            int row = f >> 4, c4 = f & 15;
            size_t go = (size_t)row * HD + c4 * 4;
            cpa16(&Kh[row*KST + c4*4], Khg + go);
            cpa16(&Kl[row*KST + c4*4], Klg + go);
            cpa16(&Vh[row*VST + c4*4], Vhg + go);
            cpa16(&Vl[row*VST + c4*4], Vlg + go);
        }
        if (tid < 16) cpa16(&ms[tid*4], mrow + tid*4);
        CPCOMMIT();
    }

    CPWAIT(1);          // Q staged (k-tile 0 may still be in flight)
    __syncthreads();

    uint32_t qh[8][4], ql[8][4];
    #pragma unroll
    for (int ks = 0; ks < 8; ks++) {
        const int kk = ks * 8 + cq;
        split2(Ps[(rb  )*PST + kk  ], qh[ks][0], ql[ks][0]);
        split2(Ps[(rb+8)*PST + kk  ], qh[ks][1], ql[ks][1]);
        split2(Ps[(rb  )*PST + kk+4], qh[ks][2], ql[ks][2]);
        split2(Ps[(rb+8)*PST + kk+4], qh[ks][3], ql[ks][3]);
    }
    // Ps rows read above are warp-local; P writes below are to the same rows.

    float acc[8][4];
    float mi[2] = {-1e30f, -1e30f}, li[2] = {0.f, 0.f};
    #pragma unroll
    for (int nt = 0; nt < 8; nt++)
        #pragma unroll
        for (int e = 0; e < 4; e++) acc[nt][e] = 0.f;

    for (int t = 0; t < SEQ / BKV; t++) {
        const int cur = t & 1, nxt = cur ^ 1;
        if (t < SEQ / BKV - 1) {
            const int k0 = (t + 1) * BKV;
            #pragma unroll
            for (int it = 0; it < 4; it++) {
                int f = tid + 256 * it;
                int row = f >> 4, c4 = f & 15;
                size_t go = (size_t)(k0 + row) * HD + c4 * 4;
                cpa16(&Kh[(nxt*BKV+row)*KST + c4*4], Khg + go);
                cpa16(&Kl[(nxt*BKV+row)*KST + c4*4], Klg + go);
                cpa16(&Vh[(nxt*BKV+row)*VST + c4*4], Vhg + go);
                cpa16(&Vl[(nxt*BKV+row)*VST + c4*4], Vlg + go);
            }
            if (tid < 16) cpa16(&ms[nxt*BKV + tid*4], mrow + k0 + tid*4);
            CPCOMMIT();
            CPWAIT(1);
        } else {
            CPWAIT(0);
        }
        __syncthreads();

        const float* KhC = Kh + cur * BKV * KST;
        const float* KlC = Kl + cur * BKV * KST;
        const float* VhC = Vh + cur * BKV * VST;
        const float* VlC = Vl + cur * BKV * VST;
        const int*   msC = ms + cur * BKV;

        // ---- S = Q @ K^T ----
        float s[8][4];
        #pragma unroll
        for (int nt = 0; nt < 8; nt++)
            #pragma unroll
            for (int e = 0; e < 4; e++) s[nt][e] = 0.f;

        #pragma unroll
        for (int ks = 0; ks < 8; ks++) {
            const int kk = ks * 8 + cq;
            uint32_t bh[8][2], bl[8][2];
            #pragma unroll
            for (int nt = 0; nt < 8; nt++) {
                int nn = nt * 8 + g;
                bh[nt][0] = __float_as_uint(KhC[nn*KST + kk  ]);
                bh[nt][1] = __float_as_uint(KhC[nn*KST + kk+4]);
                bl[nt][0] = __float_as_uint(KlC[nn*KST + kk  ]);
                bl[nt][1] = __float_as_uint(KlC[nn*KST + kk+4]);
            }
            #pragma unroll
            for (int nt = 0; nt < 8; nt++) {
                mma8(s[nt], qh[ks], bh[nt]);
                mma8(s[nt], ql[ks], bh[nt]);
                mma8(s[nt], qh[ks], bl[nt]);
            }
        }

        // ---- mask + online softmax ----
        float mx0 = -1e30f, mx1 = -1e30f;
        #pragma unroll
        for (int nt = 0; nt < 8; nt++) {
            #pragma unroll
            for (int j = 0; j < 2; j++) {
                int mv = msC[nt*8 + 2*cq + j];
                float v0 = mv ? s[nt][j]   : -1e30f;
                float v1 = mv ? s[nt][2+j] : -1e30f;
                s[nt][j] = v0; s[nt][2+j] = v1;
                mx0 = fmaxf(mx0, v0); mx1 = fmaxf(mx1, v1);
            }
        }
        mx0 = fmaxf(mx0, __shfl_xor_sync(0xffffffffu, mx0, 1));
        mx0 = fmaxf(mx0, __shfl_xor_sync(0xffffffffu, mx0, 2));
        mx1 = fmaxf(mx1, __shfl_xor_sync(0xffffffffu, mx1, 1));
        mx1 = fmaxf(mx1, __shfl_xor_sync(0xffffffffu, mx1, 2));

        float mn0 = fmaxf(mi[0], mx0), mn1 = fmaxf(mi[1], mx1);
        float cr0 = __expf(mi[0] - mn0), cr1 = __expf(mi[1] - mn1);
        float sum0 = 0.f, sum1 = 0.f;
        #pragma unroll
        for (int nt = 0; nt < 8; nt++) {
            float p0 = __expf(s[nt][0] - mn0);
            float p1 = __expf(s[nt][1] - mn0);
            float p2 = __expf(s[nt][2] - mn1);
            float p3 = __expf(s[nt][3] - mn1);
            sum0 += p0 + p1; sum1 += p2 + p3;
            *(float2*)&Ps[(rb  )*PST + nt*8 + 2*cq] = make_float2(p0, p1);
            *(float2*)&Ps[(rb+8)*PST + nt*8 + 2*cq] = make_float2(p2, p3);
            acc[nt][0] *= cr0; acc[nt][1] *= cr0;
            acc[nt][2] *= cr1; acc[nt][3] *= cr1;
        }
        sum0 += __shfl_xor_sync(0xffffffffu, sum0, 1);
        sum0 += __shfl_xor_sync(0xffffffffu, sum0, 2);
        sum1 += __shfl_xor_sync(0xffffffffu, sum1, 1);
        sum1 += __shfl_xor_sync(0xffffffffu, sum1, 2);
        li[0] = li[0] * cr0 + sum0; mi[0] = mn0;
        li[1] = li[1] * cr1 + sum1; mi[1] = mn1;
        __syncwarp();   // P tile is warp-local

        // ---- O += P @ V ----
        #pragma unroll
        for (int ks = 0; ks < 8; ks++) {
            const int kk = ks * 8 + cq;
            uint32_t ph[4], pl[4];
            split2(Ps[(rb  )*PST + kk  ], ph[0], pl[0]);
            split2(Ps[(rb+8)*PST + kk  ], ph[1], pl[1]);
            split2(Ps[(rb  )*PST + kk+4], ph[2], pl[2]);
            split2(Ps[(rb+8)*PST + kk+4], ph[3], pl[3]);
            uint32_t vh[8][2], vl[8][2];
            #pragma unroll
            for (int nt = 0; nt < 8; nt++) {
                int dd = nt * 8 + g;
                vh[nt][0] = __float_as_uint(VhC[(kk  )*VST + dd]);
                vh[nt][1] = __float_as_uint(VhC[(kk+4)*VST + dd]);
                vl[nt][0] = __float_as_uint(VlC[(kk  )*VST + dd]);
                vl[nt][1] = __float_as_uint(VlC[(kk+4)*VST + dd]);
            }
            #pragma unroll
            for (int nt = 0; nt < 8; nt++) {
                mma8(acc[nt], ph, vh[nt]);
                mma8(acc[nt], pl, vh[nt]);
                mma8(acc[nt], ph, vl[nt]);
            }
        }
        __syncthreads();
    }

    // ---- epilogue ----
    float inv0 = 1.f / li[0], inv1 = 1.f / li[1];
    #pragma unroll
    for (int nt = 0; nt < 8; nt++) {
        int col = h * 64 + nt * 8 + 2 * cq;
        size_t r0 = (size_t)(n * SEQ + q0 + rb) * EMB + col;
        size_t r1 = (size_t)(n * SEQ + q0 + rb + 8) * EMB + col;
        *(float2*)&g_ao[r0] = make_float2(acc[nt][0]*inv0, acc[nt][1]*inv0);
        *(float2*)&g_ao[r1] = make_float2(acc[nt][2]*inv1, acc[nt][3]*inv1);
    }
}

// ============================================================
extern "C" void kernel_launch(void* const* d_in, const int* in_sizes, int n_in,
                              void* d_out, int out_size)
{
    const float* values = (const float*)d_in[0];
    const float* keys   = (const float*)d_in[1];
    const float* query  = (const float*)d_in[2];
    const int*   mask   = (const int*)  d_in[3];
    const float* Wv     = (const float*)d_in[4];
    const float* Wk     = (const float*)d_in[5];
    const float* Wq     = (const float*)d_in[6];
    const float* Wo     = (const float*)d_in[7];
    const float* bo     = (const float*)d_in[8];

    split_w<<<dim3(EMB*EMB/256, 4), 256>>>(Wv, Wk, Wq, Wo);

    cudaFuncSetAttribute(proj_kernel, cudaFuncAttributeMaxDynamicSharedMemorySize, GEMM_SMEM);
    proj_kernel<<<dim3(EMB/128, NROWS/128, 3), 256, GEMM_SMEM>>>(values, keys, query);

    cudaFuncSetAttribute(flash_kernel, cudaFuncAttributeMaxDynamicSharedMemorySize, FLASH_SMEM);
    flash_kernel<<<dim3(SEQ/BQF, N_B*H), 256, FLASH_SMEM>>>(mask);

    cudaFuncSetAttribute(out_kernel, cudaFuncAttributeMaxDynamicSharedMemorySize, GEMM_SMEM);
    out_kernel<<<dim3(EMB/128, NROWS/128), 256, GEMM_SMEM>>>(bo, (float*)d_out);
}

// round 5
// speedup vs baseline: 1.6625x; 1.0195x over previous
#include <cuda_runtime.h>
#include <stdint.h>

#define N_B   8
#define SEQ   2048
#define EMB   512
#define H     8
#define HD    64
#define NROWS (N_B*SEQ)
#define HSZ   ((size_t)N_B*H*SEQ*HD)

// -------- scratch (no cudaMalloc allowed) --------
__device__ float g_whi[4*EMB*EMB], g_wlo[4*EMB*EMB];
__device__ float g_qs [HSZ];                  // raw fp32, pre-scaled by 0.125
__device__ float g_khi[HSZ], g_klo[HSZ];
__device__ float g_vhi[HSZ], g_vlo[HSZ];
__device__ float g_ao[(size_t)NROWS*EMB];

// ---------------- helpers ----------------
__device__ __forceinline__ uint32_t f2tf(float x) {
    uint32_t r; asm("cvt.rna.tf32.f32 %0, %1;" : "=r"(r) : "f"(x)); return r;
}
__device__ __forceinline__ void split2(float x, uint32_t &hi, uint32_t &lo) {
    hi = f2tf(x);
    lo = f2tf(x - __uint_as_float(hi));
}
__device__ __forceinline__ void mma8(float c[4], const uint32_t a[4], const uint32_t b[2]) {
    asm volatile(
      "mma.sync.aligned.m16n8k8.row.col.f32.tf32.tf32.f32 "
      "{%0,%1,%2,%3},{%4,%5,%6,%7},{%8,%9},{%0,%1,%2,%3};\n"
      : "+f"(c[0]), "+f"(c[1]), "+f"(c[2]), "+f"(c[3])
      : "r"(a[0]), "r"(a[1]), "r"(a[2]), "r"(a[3]), "r"(b[0]), "r"(b[1]));
}
__device__ __forceinline__ void cpa16(void* s, const void* g) {
    uint32_t sa = (uint32_t)__cvta_generic_to_shared(s);
    asm volatile("cp.async.cg.shared.global [%0], [%1], 16;" :: "r"(sa), "l"(g) : "memory");
}
#define CPCOMMIT() asm volatile("cp.async.commit_group;" ::: "memory")
#define CPWAIT(n)  asm volatile("cp.async.wait_group %0;" :: "n"(n) : "memory")

// ============================================================
// Pre-split weights
// ============================================================
__global__ __launch_bounds__(256) void split_w(
    const float* __restrict__ Wv, const float* __restrict__ Wk,
    const float* __restrict__ Wq, const float* __restrict__ Wo)
{
    const int slot = blockIdx.y;
    const float* src = (slot==0)?Wv:(slot==1)?Wk:(slot==2)?Wq:Wo;
    int i = blockIdx.x * 256 + threadIdx.x;
    float x = src[i];
    uint32_t hi, lo; split2(x, hi, lo);
    g_whi[(size_t)slot*EMB*EMB + i] = __uint_as_float(hi);
    g_wlo[(size_t)slot*EMB*EMB + i] = __uint_as_float(lo);
}

// ============================================================
// Double-buffered 3xTF32 GEMM core, 2 CTAs/SM.
// ============================================================
#define AST 36
#define BST 136
#define GEMM_SMEM ((2*128*AST + 2*2*32*BST) * 4)

__device__ __forceinline__ void gemm_prefetch(
    const float* __restrict__ X, const float* __restrict__ Whi,
    const float* __restrict__ Wlo, float (*As)[AST], float (*Bh)[BST],
    float (*Bl)[BST], int m0, int n0, int k0, int buf, int tid)
{
    #pragma unroll
    for (int it = 0; it < 4; it++) {
        int f = tid + 256 * it;
        int row = f >> 3, c4 = f & 7;
        cpa16(&As[buf*128 + row][c4*4], X + (size_t)(m0+row)*EMB + k0 + c4*4);
    }
    #pragma unroll
    for (int it = 0; it < 4; it++) {
        int f = tid + 256 * it;
        int row = f >> 5, c4 = f & 31;
        cpa16(&Bh[buf*32 + row][c4*4], Whi + (size_t)(k0+row)*EMB + n0 + c4*4);
        cpa16(&Bl[buf*32 + row][c4*4], Wlo + (size_t)(k0+row)*EMB + n0 + c4*4);
    }
}

__device__ __forceinline__ void gemm_core(
    const float* __restrict__ X, const float* __restrict__ Whi,
    const float* __restrict__ Wlo, float* sm, float c[2][8][4],
    int m0, int n0, int tid)
{
    float (*As)[AST] = reinterpret_cast<float(*)[AST]>(sm);
    float (*Bh)[BST] = reinterpret_cast<float(*)[BST]>(sm + 2*128*AST);
    float (*Bl)[BST] = reinterpret_cast<float(*)[BST]>(sm + 2*128*AST + 2*32*BST);

    const int lane = tid & 31, w = tid >> 5;
    const int g = lane >> 2, cq = lane & 3;
    const int wm = (w & 3) * 32, wn = (w >> 2) * 64;

    #pragma unroll
    for (int mt = 0; mt < 2; mt++)
        #pragma unroll
        for (int nt = 0; nt < 8; nt++)
            #pragma unroll
            for (int e = 0; e < 4; e++) c[mt][nt][e] = 0.f;

    gemm_prefetch(X, Whi, Wlo, As, Bh, Bl, m0, n0, 0, 0, tid);
    CPCOMMIT();

    for (int t = 0; t < 16; t++) {
        if (t < 15) {
            gemm_prefetch(X, Whi, Wlo, As, Bh, Bl, m0, n0, (t+1)*32, (t+1)&1, tid);
            CPCOMMIT();
            CPWAIT(1);
        } else {
            CPWAIT(0);
        }
        __syncthreads();

        const int ab = (t & 1) * 128, bb = (t & 1) * 32;
        #pragma unroll
        for (int ks = 0; ks < 4; ks++) {
            const int kk = ks * 8 + cq;
            uint32_t ahi[2][4], alo[2][4];
            #pragma unroll
            for (int mt = 0; mt < 2; mt++) {
                int rb = ab + wm + mt*16 + g;
                split2(As[rb    ][kk    ], ahi[mt][0], alo[mt][0]);
                split2(As[rb + 8][kk    ], ahi[mt][1], alo[mt][1]);
                split2(As[rb    ][kk + 4], ahi[mt][2], alo[mt][2]);
                split2(As[rb + 8][kk + 4], ahi[mt][3], alo[mt][3]);
            }
            uint32_t bhi[8][2], blo[8][2];
            #pragma unroll
            for (int nt = 0; nt < 8; nt++) {
                int nn = wn + nt*8 + g;
                bhi[nt][0] = __float_as_uint(Bh[bb+kk  ][nn]);
                bhi[nt][1] = __float_as_uint(Bh[bb+kk+4][nn]);
                blo[nt][0] = __float_as_uint(Bl[bb+kk  ][nn]);
                blo[nt][1] = __float_as_uint(Bl[bb+kk+4][nn]);
            }
            #pragma unroll
            for (int mt = 0; mt < 2; mt++)
                #pragma unroll
                for (int nt = 0; nt < 8; nt++) {
                    mma8(c[mt][nt], ahi[mt], bhi[nt]);
                    mma8(c[mt][nt], alo[mt], bhi[nt]);
                    mma8(c[mt][nt], ahi[mt], blo[nt]);
                }
        }
        __syncthreads();
    }
}

// ============================================================
// Projections: K/V written pre-split hi/lo; Q written raw*0.125
// ============================================================
__global__ __launch_bounds__(256, 2) void proj_kernel(
    const float* __restrict__ values, const float* __restrict__ keys,
    const float* __restrict__ query)
{
    extern __shared__ float sm[];
    const int which = blockIdx.z;   // 0:v 1:k 2:q
    const float* X = (which == 0) ? values : (which == 1) ? keys : query;
    const float* Whi = g_whi + (size_t)which * EMB * EMB;
    const float* Wlo = g_wlo + (size_t)which * EMB * EMB;

    const int m0 = blockIdx.y * 128, n0 = blockIdx.x * 128;
    float c[2][8][4];
    gemm_core(X, Whi, Wlo, sm, c, m0, n0, threadIdx.x);

    const int lane = threadIdx.x & 31, w = threadIdx.x >> 5;
    const int g = lane >> 2, cq = lane & 3;
    const int wm = (w & 3) * 32, wn = (w >> 2) * 64;

    if (which == 2) {
        #pragma unroll
        for (int mt = 0; mt < 2; mt++)
            #pragma unroll
            for (int half = 0; half < 2; half++) {
                int row = m0 + wm + mt*16 + g + half*8;
                int n = row >> 11, s = row & 2047;
                #pragma unroll
                for (int nt = 0; nt < 8; nt++) {
                    int col = n0 + wn + nt*8 + 2*cq;
                    int h = col >> 6, d = col & 63;
                    size_t base = (((size_t)(n * H + h)) * SEQ + s) * HD + d;
                    *(float2*)&g_qs[base] = make_float2(
                        c[mt][nt][half*2+0] * 0.125f, c[mt][nt][half*2+1] * 0.125f);
                }
            }
    } else {
        float* dhi = (which == 0) ? g_vhi : g_khi;
        float* dlo = (which == 0) ? g_vlo : g_klo;
        #pragma unroll
        for (int mt = 0; mt < 2; mt++)
            #pragma unroll
            for (int half = 0; half < 2; half++) {
                int row = m0 + wm + mt*16 + g + half*8;
                int n = row >> 11, s = row & 2047;
                #pragma unroll
                for (int nt = 0; nt < 8; nt++) {
                    int col = n0 + wn + nt*8 + 2*cq;
                    int h = col >> 6, d = col & 63;
                    size_t base = (((size_t)(n * H + h)) * SEQ + s) * HD + d;
                    uint32_t h0, l0, h1, l1;
                    split2(c[mt][nt][half*2+0], h0, l0);
                    split2(c[mt][nt][half*2+1], h1, l1);
                    *(float2*)&dhi[base] = make_float2(__uint_as_float(h0), __uint_as_float(h1));
                    *(float2*)&dlo[base] = make_float2(__uint_as_float(l0), __uint_as_float(l1));
                }
            }
    }
}

// ============================================================
// Output GEMM: out = g_ao @ Wo + bo
// ============================================================
__global__ __launch_bounds__(256, 2) void out_kernel(
    const float* __restrict__ bo, float* __restrict__ out)
{
    extern __shared__ float sm[];
    const int m0 = blockIdx.y * 128, n0 = blockIdx.x * 128;
    float c[2][8][4];
    gemm_core(g_ao, g_whi + (size_t)3*EMB*EMB, g_wlo + (size_t)3*EMB*EMB,
              sm, c, m0, n0, threadIdx.x);

    const int lane = threadIdx.x & 31, w = threadIdx.x >> 5;
    const int g = lane >> 2, cq = lane & 3;
    const int wm = (w & 3) * 32, wn = (w >> 2) * 64;

    #pragma unroll
    for (int mt = 0; mt < 2; mt++)
        #pragma unroll
        for (int half = 0; half < 2; half++) {
            size_t row = m0 + wm + mt*16 + g + half*8;
            #pragma unroll
            for (int nt = 0; nt < 8; nt++) {
                int col = n0 + wn + nt*8 + 2*cq;
                float2 v = make_float2(c[mt][nt][half*2+0] + bo[col],
                                       c[mt][nt][half*2+1] + bo[col+1]);
                *(float2*)&out[row * EMB + col] = v;
            }
        }
}

// ============================================================
// Flash attention: BQ=128, BKV=32, double-buffered, 2 CTAs/SM.
// 8 warps, warp w owns q-rows [w*16, w*16+16).
// Q kept RAW in registers (32/thread), split inline per ks-step.
// ============================================================
#define BQF 128
#define BKV 32
#define KST 68
#define VST 72
#define PST 36
#define FL_KH 0
#define FL_KL (FL_KH + 2*BKV*KST)     // 4352
#define FL_VH (FL_KL + 2*BKV*KST)     // 8704
#define FL_VL (FL_VH + 2*BKV*VST)     // 13312
#define FL_PS (FL_VL + 2*BKV*VST)     // 17920
#define FL_MS (FL_PS + BQF*PST)       // 22528
#define FLASH_SMEM ((FL_MS + 2*BKV) * 4)

__global__ __launch_bounds__(256, 2) void flash_kernel(const int* __restrict__ mask)
{
    extern __shared__ float sm[];
    float* Kh = sm + FL_KH;
    float* Kl = sm + FL_KL;
    float* Vh = sm + FL_VH;
    float* Vl = sm + FL_VL;
    float* Ps = sm + FL_PS;
    int*   ms = (int*)(sm + FL_MS);

    const int tid = threadIdx.x;
    const int lane = tid & 31, w = tid >> 5;
    const int g = lane >> 2, cq = lane & 3;
    const int q0 = blockIdx.x * BQF;
    const int nh = blockIdx.y;
    const int n = nh >> 3, h = nh & 7;
    const float* Qg  = g_qs  + (size_t)nh * SEQ * HD;
    const float* Khg = g_khi + (size_t)nh * SEQ * HD;
    const float* Klg = g_klo + (size_t)nh * SEQ * HD;
    const float* Vhg = g_vhi + (size_t)nh * SEQ * HD;
    const float* Vlg = g_vlo + (size_t)nh * SEQ * HD;
    const int* mrow = mask + n * SEQ;
    const int rb = w * 16 + g;

    // ---- stage Q through smem (K region, stride 68), read raw to regs ----
    {
        float* Qstage = sm;   // 128 rows x stride 68 = 8704 floats (= Kh+Kl)
        #pragma unroll
        for (int it = 0; it < 8; it++) {
            int f = tid + 256 * it;
            int row = f >> 4, c4 = f & 15;
            cpa16(&Qstage[row*KST + c4*4], Qg + (size_t)(q0+row)*HD + c4*4);
        }
        CPCOMMIT(); CPWAIT(0);
        __syncthreads();
        // fall through to register read below, then sync before reuse
    }

    float qraw[8][4];
    #pragma unroll
    for (int ks = 0; ks < 8; ks++) {
        const int kk = ks * 8 + cq;
        qraw[ks][0] = sm[(rb  )*KST + kk  ];
        qraw[ks][1] = sm[(rb+8)*KST + kk  ];
        qraw[ks][2] = sm[(rb  )*KST + kk+4];
        qraw[ks][3] = sm[(rb+8)*KST + kk+4];
    }
    __syncthreads();   // everyone done reading Q staging; K buffers reusable

    // ---- prefetch k-tile 0 ----
    #pragma unroll
    for (int it = 0; it < 2; it++) {
        int f = tid + 256 * it;
        int row = f >> 4, c4 = f & 15;
        size_t go = (size_t)row * HD + c4 * 4;
        cpa16(&Kh[row*KST + c4*4], Khg + go);
        cpa16(&Kl[row*KST + c4*4], Klg + go);
        cpa16(&Vh[row*VST + c4*4], Vhg + go);
        cpa16(&Vl[row*VST + c4*4], Vlg + go);
    }
    if (tid < 8) cpa16(&ms[tid*4], mrow + tid*4);
    CPCOMMIT();

    float acc[8][4];
    float mi[2] = {-1e30f, -1e30f}, li[2] = {0.f, 0.f};
    #pragma unroll
    for (int nt = 0; nt < 8; nt++)
        #pragma unroll
        for (int e = 0; e < 4; e++) acc[nt][e] = 0.f;

    for (int t = 0; t < SEQ / BKV; t++) {
        const int cur = t & 1, nxt = cur ^ 1;
        if (t < SEQ / BKV - 1) {
            const int k0 = (t + 1) * BKV;
            #pragma unroll
            for (int it = 0; it < 2; it++) {
                int f = tid + 256 * it;
                int row = f >> 4, c4 = f & 15;
                size_t go = (size_t)(k0 + row) * HD + c4 * 4;
                cpa16(&Kh[(nxt*BKV+row)*KST + c4*4], Khg + go);
                cpa16(&Kl[(nxt*BKV+row)*KST + c4*4], Klg + go);
                cpa16(&Vh[(nxt*BKV+row)*VST + c4*4], Vhg + go);
                cpa16(&Vl[(nxt*BKV+row)*VST + c4*4], Vlg + go);
            }
            if (tid < 8) cpa16(&ms[nxt*BKV + tid*4], mrow + k0 + tid*4);
            CPCOMMIT();
            CPWAIT(1);
        } else {
            CPWAIT(0);
        }
        __syncthreads();

        const float* KhC = Kh + cur * BKV * KST;
        const float* KlC = Kl + cur * BKV * KST;
        const float* VhC = Vh + cur * BKV * VST;
        const float* VlC = Vl + cur * BKV * VST;
        const int*   msC = ms + cur * BKV;

        // ---- S = Q @ K^T ----
        float s[4][4];
        #pragma unroll
        for (int nt = 0; nt < 4; nt++)
            #pragma unroll
            for (int e = 0; e < 4; e++) s[nt][e] = 0.f;

        #pragma unroll
        for (int ks = 0; ks < 8; ks++) {
            const int kk = ks * 8 + cq;
            uint32_t qh[4], ql[4];
            split2(qraw[ks][0], qh[0], ql[0]);
            split2(qraw[ks][1], qh[1], ql[1]);
            split2(qraw[ks][2], qh[2], ql[2]);
            split2(qraw[ks][3], qh[3], ql[3]);
            uint32_t bh[4][2], bl[4][2];
            #pragma unroll
            for (int nt = 0; nt < 4; nt++) {
                int nn = nt * 8 + g;
                bh[nt][0] = __float_as_uint(KhC[nn*KST + kk  ]);
                bh[nt][1] = __float_as_uint(KhC[nn*KST + kk+4]);
                bl[nt][0] = __float_as_uint(KlC[nn*KST + kk  ]);
                bl[nt][1] = __float_as_uint(KlC[nn*KST + kk+4]);
            }
            #pragma unroll
            for (int nt = 0; nt < 4; nt++) {
                mma8(s[nt], qh, bh[nt]);
                mma8(s[nt], ql, bh[nt]);
                mma8(s[nt], qh, bl[nt]);
            }
        }

        // ---- mask + online softmax ----
        float mx0 = -1e30f, mx1 = -1e30f;
        #pragma unroll
        for (int nt = 0; nt < 4; nt++) {
            #pragma unroll
            for (int j = 0; j < 2; j++) {
                int mv = msC[nt*8 + 2*cq + j];
                float v0 = mv ? s[nt][j]   : -1e30f;
                float v1 = mv ? s[nt][2+j] : -1e30f;
                s[nt][j] = v0; s[nt][2+j] = v1;
                mx0 = fmaxf(mx0, v0); mx1 = fmaxf(mx1, v1);
            }
        }
        mx0 = fmaxf(mx0, __shfl_xor_sync(0xffffffffu, mx0, 1));
        mx0 = fmaxf(mx0, __shfl_xor_sync(0xffffffffu, mx0, 2));
        mx1 = fmaxf(mx1, __shfl_xor_sync(0xffffffffu, mx1, 1));
        mx1 = fmaxf(mx1, __shfl_xor_sync(0xffffffffu, mx1, 2));

        float mn0 = fmaxf(mi[0], mx0), mn1 = fmaxf(mi[1], mx1);
        float cr0 = __expf(mi[0] - mn0), cr1 = __expf(mi[1] - mn1);
        float sum0 = 0.f, sum1 = 0.f;
        #pragma unroll
        for (int nt = 0; nt < 4; nt++) {
            float p0 = __expf(s[nt][0] - mn0);
            float p1 = __expf(s[nt][1] - mn0);
            float p2 = __expf(s[nt][2] - mn1);
            float p3 = __expf(s[nt][3] - mn1);
            sum0 += p0 + p1; sum1 += p2 + p3;
            *(float2*)&Ps[(rb  )*PST + nt*8 + 2*cq] = make_float2(p0, p1);
            *(float2*)&Ps[(rb+8)*PST + nt*8 + 2*cq] = make_float2(p2, p3);
        }
        sum0 += __shfl_xor_sync(0xffffffffu, sum0, 1);
        sum0 += __shfl_xor_sync(0xffffffffu, sum0, 2);
        sum1 += __shfl_xor_sync(0xffffffffu, sum1, 1);
        sum1 += __shfl_xor_sync(0xffffffffu, sum1, 2);
        li[0] = li[0] * cr0 + sum0; mi[0] = mn0;
        li[1] = li[1] * cr1 + sum1; mi[1] = mn1;
        #pragma unroll
        for (int nt = 0; nt < 8; nt++) {
            acc[nt][0] *= cr0; acc[nt][1] *= cr0;
            acc[nt][2] *= cr1; acc[nt][3] *= cr1;
        }
        __syncwarp();   // P tile is warp-local

        // ---- O += P @ V ----
        #pragma unroll
        for (int ks = 0; ks < 4; ks++) {
            const int kk = ks * 8 + cq;
            uint32_t ph[4], pl[4];
            split2(Ps[(rb  )*PST + kk  ], ph[0], pl[0]);
            split2(Ps[(rb+8)*PST + kk  ], ph[1], pl[1]);
            split2(Ps[(rb  )*PST + kk+4], ph[2], pl[2]);
            split2(Ps[(rb+8)*PST + kk+4], ph[3], pl[3]);
            uint32_t vh[8][2], vl[8][2];
            #pragma unroll
            for (int nt = 0; nt < 8; nt++) {
                int dd = nt * 8 + g;
                vh[nt][0] = __float_as_uint(VhC[(kk  )*VST + dd]);
                vh[nt][1] = __float_as_uint(VhC[(kk+4)*VST + dd]);
                vl[nt][0] = __float_as_uint(VlC[(kk  )*VST + dd]);
                vl[nt][1] = __float_as_uint(VlC[(kk+4)*VST + dd]);
            }
            #pragma unroll
            for (int nt = 0; nt < 8; nt++) {
                mma8(acc[nt], ph, vh[nt]);
                mma8(acc[nt], pl, vh[nt]);
                mma8(acc[nt], ph, vl[nt]);
            }
        }
        __syncthreads();
    }

    // ---- epilogue ----
    float inv0 = 1.f / li[0], inv1 = 1.f / li[1];
    #pragma unroll
    for (int nt = 0; nt < 8; nt++) {
        int col = h * 64 + nt * 8 + 2 * cq;
        size_t r0 = (size_t)(n * SEQ + q0 + rb) * EMB + col;
        size_t r1 = (size_t)(n * SEQ + q0 + rb + 8) * EMB + col;
        *(float2*)&g_ao[r0] = make_float2(acc[nt][0]*inv0, acc[nt][1]*inv0);
        *(float2*)&g_ao[r1] = make_float2(acc[nt][2]*inv1, acc[nt][3]*inv1);
    }
}

// ============================================================
extern "C" void kernel_launch(void* const* d_in, const int* in_sizes, int n_in,
                              void* d_out, int out_size)
{
    const float* values = (const float*)d_in[0];
    const float* keys   = (const float*)d_in[1];
    const float* query  = (const float*)d_in[2];
    const int*   mask   = (const int*)  d_in[3];
    const float* Wv     = (const float*)d_in[4];
    const float* Wk     = (const float*)d_in[5];
    const float* Wq     = (const float*)d_in[6];
    const float* Wo     = (const float*)d_in[7];
    const float* bo     = (const float*)d_in[8];

    split_w<<<dim3(EMB*EMB/256, 4), 256>>>(Wv, Wk, Wq, Wo);

    cudaFuncSetAttribute(proj_kernel, cudaFuncAttributeMaxDynamicSharedMemorySize, GEMM_SMEM);
    proj_kernel<<<dim3(EMB/128, NROWS/128, 3), 256, GEMM_SMEM>>>(values, keys, query);

    cudaFuncSetAttribute(flash_kernel, cudaFuncAttributeMaxDynamicSharedMemorySize, FLASH_SMEM);
    flash_kernel<<<dim3(SEQ/BQF, N_B*H), 256, FLASH_SMEM>>>(mask);

    cudaFuncSetAttribute(out_kernel, cudaFuncAttributeMaxDynamicSharedMemorySize, GEMM_SMEM);
    out_kernel<<<dim3(EMB/128, NROWS/128), 256, GEMM_SMEM>>>(bo, (float*)d_out);
}

// round 6
// speedup vs baseline: 2.9297x; 1.7622x over previous
#include <cuda_runtime.h>
#include <cuda_bf16.h>
#include <stdint.h>

#define N_B   8
#define SEQ   2048
#define EMB   512
#define H     8
#define HD    64
#define NROWS (N_B*SEQ)
#define NH    (N_B*H)

// -------- scratch (no cudaMalloc allowed) --------
// weights: bf16 pairs packed along k: [slot][kp<256][n<512]
__device__ uint32_t g_wh[4*256*EMB], g_wl[4*256*EMB];
// q,k: bf16 pairs packed along d: [(nh*SEQ+s)*32 + dp]
__device__ uint32_t g_qh[(size_t)NH*SEQ*32], g_ql[(size_t)NH*SEQ*32];
__device__ uint32_t g_kh[(size_t)NH*SEQ*32], g_kl[(size_t)NH*SEQ*32];
// v: bf16 pairs packed along s: [(nh*(SEQ/2)+sp)*64 + d]
__device__ uint32_t g_vh[(size_t)NH*(SEQ/2)*64], g_vl[(size_t)NH*(SEQ/2)*64];
__device__ float g_ao[(size_t)NROWS*EMB];

// ---------------- helpers ----------------
__device__ __forceinline__ uint32_t pack2(__nv_bfloat16 a, __nv_bfloat16 b) {
    return ((uint32_t)__bfloat16_as_ushort(b) << 16) | (uint32_t)__bfloat16_as_ushort(a);
}
__device__ __forceinline__ void splitb(float x, __nv_bfloat16 &h, __nv_bfloat16 &l) {
    h = __float2bfloat16_rn(x);
    l = __float2bfloat16_rn(x - __bfloat162float(h));
}
__device__ __forceinline__ void split_pack(float x0, float x1, uint32_t &hi, uint32_t &lo) {
    __nv_bfloat16 h0, l0, h1, l1;
    splitb(x0, h0, l0); splitb(x1, h1, l1);
    hi = pack2(h0, h1); lo = pack2(l0, l1);
}
__device__ __forceinline__ void mmab(float c[4], const uint32_t a[4], const uint32_t b[2]) {
    asm volatile(
      "mma.sync.aligned.m16n8k16.row.col.f32.bf16.bf16.f32 "
      "{%0,%1,%2,%3},{%4,%5,%6,%7},{%8,%9},{%0,%1,%2,%3};\n"
      : "+f"(c[0]), "+f"(c[1]), "+f"(c[2]), "+f"(c[3])
      : "r"(a[0]), "r"(a[1]), "r"(a[2]), "r"(a[3]), "r"(b[0]), "r"(b[1]));
}
__device__ __forceinline__ void cpa16(void* s, const void* g) {
    uint32_t sa = (uint32_t)__cvta_generic_to_shared(s);
    asm volatile("cp.async.cg.shared.global [%0], [%1], 16;" :: "r"(sa), "l"(g) : "memory");
}
#define CPCOMMIT() asm volatile("cp.async.commit_group;" ::: "memory")
#define CPWAIT(n)  asm volatile("cp.async.wait_group %0;" :: "n"(n) : "memory")

// ============================================================
// Pre-split weights -> bf16 hi/lo pairs packed along k.
// ============================================================
__global__ __launch_bounds__(256) void split_w(
    const float* __restrict__ Wv, const float* __restrict__ Wk,
    const float* __restrict__ Wq, const float* __restrict__ Wo)
{
    const int slot = blockIdx.y;
    const float* src = (slot==0)?Wv:(slot==1)?Wk:(slot==2)?Wq:Wo;
    int i = blockIdx.x * 256 + threadIdx.x;      // 0 .. 131071
    int kp = i >> 9, n = i & 511;
    float x0 = src[(2*kp  ) * EMB + n];
    float x1 = src[(2*kp+1) * EMB + n];
    uint32_t hi, lo; split_pack(x0, x1, hi, lo);
    g_wh[(size_t)slot*256*EMB + i] = hi;
    g_wl[(size_t)slot*256*EMB + i] = lo;
}

// ============================================================
// bf16x3 GEMM core: C[128x128] = X(fp32) @ W(pre-split).
// 8 warps 4(m)x2(n), warp tile 32x64, ktile 32 (2 k16 steps).
// ============================================================
#define AST 36
#define BSTP 136
#define GA (2*128*AST)     // floats
#define GB (2*16*BSTP)     // u32 per array
#define GEMM_SMEM ((GA + 2*GB) * 4)

__device__ __forceinline__ void gemm_prefetch(
    const float* __restrict__ X, const uint32_t* __restrict__ Wh,
    const uint32_t* __restrict__ Wl, float* As, uint32_t* Bh, uint32_t* Bl,
    int m0, int n0, int k0, int buf, int tid)
{
    #pragma unroll
    for (int it = 0; it < 4; it++) {
        int f = tid + 256 * it;
        int row = f >> 3, c4 = f & 7;
        cpa16(&As[(buf*128 + row)*AST + c4*4], X + (size_t)(m0+row)*EMB + k0 + c4*4);
    }
    const int kp0 = k0 >> 1;
    #pragma unroll
    for (int it = 0; it < 2; it++) {
        int f = tid + 256 * it;
        int row = f >> 5, c4 = f & 31;
        cpa16(&Bh[(buf*16 + row)*BSTP + c4*4], Wh + (size_t)(kp0+row)*EMB + n0 + c4*4);
        cpa16(&Bl[(buf*16 + row)*BSTP + c4*4], Wl + (size_t)(kp0+row)*EMB + n0 + c4*4);
    }
}

__device__ __forceinline__ void gemm_core(
    const float* __restrict__ X, const uint32_t* __restrict__ Wh,
    const uint32_t* __restrict__ Wl, float* sm, float c[2][8][4],
    int m0, int n0, int tid)
{
    float* As = sm;
    uint32_t* Bh = (uint32_t*)(sm + GA);
    uint32_t* Bl = Bh + GB;

    const int lane = tid & 31, w = tid >> 5;
    const int g = lane >> 2, cq = lane & 3;
    const int wm = (w & 3) * 32, wn = (w >> 2) * 64;

    #pragma unroll
    for (int mt = 0; mt < 2; mt++)
        #pragma unroll
        for (int nt = 0; nt < 8; nt++)
            #pragma unroll
            for (int e = 0; e < 4; e++) c[mt][nt][e] = 0.f;

    gemm_prefetch(X, Wh, Wl, As, Bh, Bl, m0, n0, 0, 0, tid);
    CPCOMMIT();

    for (int t = 0; t < 16; t++) {
        if (t < 15) {
            gemm_prefetch(X, Wh, Wl, As, Bh, Bl, m0, n0, (t+1)*32, (t+1)&1, tid);
            CPCOMMIT();
            CPWAIT(1);
        } else {
            CPWAIT(0);
        }
        __syncthreads();

        const int ab = (t & 1) * 128, bb = (t & 1) * 16;
        #pragma unroll
        for (int ks = 0; ks < 2; ks++) {
            uint32_t ah[2][4], al[2][4];
            #pragma unroll
            for (int mt = 0; mt < 2; mt++) {
                int rb = ab + wm + mt*16 + g;
                int kb = ks*16 + 2*cq;
                float2 v0 = *(const float2*)&As[(rb    )*AST + kb    ];
                float2 v1 = *(const float2*)&As[(rb + 8)*AST + kb    ];
                float2 v2 = *(const float2*)&As[(rb    )*AST + kb + 8];
                float2 v3 = *(const float2*)&As[(rb + 8)*AST + kb + 8];
                split_pack(v0.x, v0.y, ah[mt][0], al[mt][0]);
                split_pack(v1.x, v1.y, ah[mt][1], al[mt][1]);
                split_pack(v2.x, v2.y, ah[mt][2], al[mt][2]);
                split_pack(v3.x, v3.y, ah[mt][3], al[mt][3]);
            }
            uint32_t bh[8][2], bl[8][2];
            #pragma unroll
            for (int nt = 0; nt < 8; nt++) {
                int nn = wn + nt*8 + g;
                int kp = bb + ks*8 + cq;
                bh[nt][0] = Bh[(kp    )*BSTP + nn];
                bh[nt][1] = Bh[(kp + 4)*BSTP + nn];
                bl[nt][0] = Bl[(kp    )*BSTP + nn];
                bl[nt][1] = Bl[(kp + 4)*BSTP + nn];
            }
            #pragma unroll
            for (int mt = 0; mt < 2; mt++)
                #pragma unroll
                for (int nt = 0; nt < 8; nt++) {
                    mmab(c[mt][nt], ah[mt], bh[nt]);
                    mmab(c[mt][nt], al[mt], bh[nt]);
                    mmab(c[mt][nt], ah[mt], bl[nt]);
                }
        }
        __syncthreads();
    }
}

// ============================================================
// Projections. Q: *0.125, d-pair packed. K: d-pair packed.
// V: s-pair packed (transpose pack via shfl).
// ============================================================
__global__ __launch_bounds__(256, 2) void proj_kernel(
    const float* __restrict__ values, const float* __restrict__ keys,
    const float* __restrict__ query)
{
    extern __shared__ float sm[];
    const int which = blockIdx.z;   // 0:v 1:k 2:q
    const float* X = (which == 0) ? values : (which == 1) ? keys : query;
    const uint32_t* Wh = g_wh + (size_t)which * 256 * EMB;
    const uint32_t* Wl = g_wl + (size_t)which * 256 * EMB;

    const int m0 = blockIdx.y * 128, n0 = blockIdx.x * 128;
    float c[2][8][4];
    gemm_core(X, Wh, Wl, sm, c, m0, n0, threadIdx.x);

    const int lane = threadIdx.x & 31, w = threadIdx.x >> 5;
    const int g = lane >> 2, cq = lane & 3;
    const int wm = (w & 3) * 32, wn = (w >> 2) * 64;

    if (which != 0) {
        // Q or K: pack (col, col+1) along d
        uint32_t* dh = (which == 2) ? g_qh : g_kh;
        uint32_t* dl = (which == 2) ? g_ql : g_kl;
        const float post = (which == 2) ? 0.125f : 1.0f;
        #pragma unroll
        for (int mt = 0; mt < 2; mt++)
            #pragma unroll
            for (int half = 0; half < 2; half++) {
                int row = m0 + wm + mt*16 + g + half*8;
                int n = row >> 11, s = row & 2047;
                #pragma unroll
                for (int nt = 0; nt < 8; nt++) {
                    int col = n0 + wn + nt*8 + 2*cq;
                    int h = col >> 6, d = col & 63;
                    size_t base = ((size_t)(n*H + h)*SEQ + s)*32 + (d >> 1);
                    uint32_t hi, lo;
                    split_pack(c[mt][nt][half*2+0]*post, c[mt][nt][half*2+1]*post, hi, lo);
                    dh[base] = hi; dl[base] = lo;
                }
            }
    } else {
        // V: pack (row, row+1) along s via partner exchange
        #pragma unroll
        for (int mt = 0; mt < 2; mt++)
            #pragma unroll
            for (int nt = 0; nt < 8; nt++) {
                float p0 = __shfl_xor_sync(0xffffffffu, c[mt][nt][0], 4);
                float p1 = __shfl_xor_sync(0xffffffffu, c[mt][nt][1], 4);
                float p2 = __shfl_xor_sync(0xffffffffu, c[mt][nt][2], 4);
                float p3 = __shfl_xor_sync(0xffffffffu, c[mt][nt][3], 4);
                if ((g & 1) == 0) {
                    int col = n0 + wn + nt*8 + 2*cq;
                    int h = col >> 6, d = col & 63;
                    #pragma unroll
                    for (int half = 0; half < 2; half++) {
                        int row = m0 + wm + mt*16 + g + half*8;  // even
                        int n = row >> 11, s = row & 2047;
                        size_t base = ((size_t)(n*H + h)*(SEQ/2) + (s >> 1))*64 + d;
                        float m0v = c[mt][nt][half*2+0], m1v = c[mt][nt][half*2+1];
                        float q0v = (half == 0) ? p0 : p2;
                        float q1v = (half == 0) ? p1 : p3;
                        uint32_t h0, l0, h1, l1;
                        split_pack(m0v, q0v, h0, l0);   // (s, s+1) at col d
                        split_pack(m1v, q1v, h1, l1);   // (s, s+1) at col d+1
                        g_vh[base    ] = h0; g_vl[base    ] = l0;
                        g_vh[base + 1] = h1; g_vl[base + 1] = l1;
                    }
                }
            }
    }
}

// ============================================================
// Output GEMM: out = g_ao @ Wo + bo
// ============================================================
__global__ __launch_bounds__(256, 2) void out_kernel(
    const float* __restrict__ bo, float* __restrict__ out)
{
    extern __shared__ float sm[];
    const int m0 = blockIdx.y * 128, n0 = blockIdx.x * 128;
    float c[2][8][4];
    gemm_core(g_ao, g_wh + (size_t)3*256*EMB, g_wl + (size_t)3*256*EMB,
              sm, c, m0, n0, threadIdx.x);

    const int lane = threadIdx.x & 31, w = threadIdx.x >> 5;
    const int g = lane >> 2, cq = lane & 3;
    const int wm = (w & 3) * 32, wn = (w >> 2) * 64;

    #pragma unroll
    for (int mt = 0; mt < 2; mt++)
        #pragma unroll
        for (int half = 0; half < 2; half++) {
            size_t row = m0 + wm + mt*16 + g + half*8;
            #pragma unroll
            for (int nt = 0; nt < 8; nt++) {
                int col = n0 + wn + nt*8 + 2*cq;
                float2 v = make_float2(c[mt][nt][half*2+0] + bo[col],
                                       c[mt][nt][half*2+1] + bo[col+1]);
                *(float2*)&out[row * EMB + col] = v;
            }
        }
}

// ============================================================
// Flash attention, bf16x3. BQ=128, BKV=32, double-buffered.
// Q frags in regs (split once). P repacked register->register.
// ============================================================
#define BQF 128
#define BKV 32
#define KSTP 36    // u32 stride, 32 dp + pad
#define VSTP 72    // u32 stride, 64 d + pad
#define FK (2*BKV*KSTP)        // u32 per K array
#define FV (2*(BKV/2)*VSTP)    // u32 per V array
#define FL_MS (2*FK + 2*FV)
#define FLASH_SMEM ((FL_MS + 2*BKV) * 4)

__global__ __launch_bounds__(256, 2) void flash_kernel(const int* __restrict__ mask)
{
    extern __shared__ uint32_t smu[];
    uint32_t* Kh = smu;
    uint32_t* Kl = Kh + FK;
    uint32_t* Vh = Kl + FK;
    uint32_t* Vl = Vh + FV;
    int*      ms = (int*)(Vl + FV);

    const int tid = threadIdx.x;
    const int lane = tid & 31, w = tid >> 5;
    const int g = lane >> 2, cq = lane & 3;
    const int q0 = blockIdx.x * BQF;
    const int nh = blockIdx.y;
    const int n = nh >> 3, h = nh & 7;
    const uint32_t* Qhg = g_qh + (size_t)nh * SEQ * 32;
    const uint32_t* Qlg = g_ql + (size_t)nh * SEQ * 32;
    const uint32_t* Khg = g_kh + (size_t)nh * SEQ * 32;
    const uint32_t* Klg = g_kl + (size_t)nh * SEQ * 32;
    const uint32_t* Vhg = g_vh + (size_t)nh * (SEQ/2) * 64;
    const uint32_t* Vlg = g_vl + (size_t)nh * (SEQ/2) * 64;
    const int* mrow = mask + n * SEQ;
    const int rb = w * 16 + g;

    // ---- prefetch k-tile 0 ----
    {
        int row = tid >> 3, c4 = tid & 7;          // K: 32 rows x 32 u32
        cpa16(&Kh[row*KSTP + c4*4], Khg + (size_t)row*32 + c4*4);
        cpa16(&Kl[row*KSTP + c4*4], Klg + (size_t)row*32 + c4*4);
        int vr = tid >> 4, vc = tid & 15;          // V: 16 rows x 64 u32
        cpa16(&Vh[vr*VSTP + vc*4], Vhg + (size_t)vr*64 + vc*4);
        cpa16(&Vl[vr*VSTP + vc*4], Vlg + (size_t)vr*64 + vc*4);
        if (tid < 8) cpa16(&ms[tid*4], mrow + tid*4);
        CPCOMMIT();
    }

    // ---- Q fragments: direct LDG, already split/packed/scaled ----
    uint32_t qh[4][4], ql[4][4];
    {
        const int r0 = q0 + rb, r1 = r0 + 8;
        #pragma unroll
        for (int ks = 0; ks < 4; ks++) {
            int d0 = ks*8 + cq, d1 = ks*8 + 4 + cq;
            qh[ks][0] = Qhg[(size_t)r0*32 + d0];
            qh[ks][1] = Qhg[(size_t)r1*32 + d0];
            qh[ks][2] = Qhg[(size_t)r0*32 + d1];
            qh[ks][3] = Qhg[(size_t)r1*32 + d1];
            ql[ks][0] = Qlg[(size_t)r0*32 + d0];
            ql[ks][1] = Qlg[(size_t)r1*32 + d0];
            ql[ks][2] = Qlg[(size_t)r0*32 + d1];
            ql[ks][3] = Qlg[(size_t)r1*32 + d1];
        }
    }

    float acc[8][4];
    float mi[2] = {-1e30f, -1e30f}, li[2] = {0.f, 0.f};
    #pragma unroll
    for (int nt = 0; nt < 8; nt++)
        #pragma unroll
        for (int e = 0; e < 4; e++) acc[nt][e] = 0.f;

    for (int t = 0; t < SEQ / BKV; t++) {
        const int cur = t & 1, nxt = cur ^ 1;
        if (t < SEQ / BKV - 1) {
            const int k0 = (t + 1) * BKV;
            int row = tid >> 3, c4 = tid & 7;
            cpa16(&Kh[(nxt*BKV+row)*KSTP + c4*4], Khg + (size_t)(k0+row)*32 + c4*4);
            cpa16(&Kl[(nxt*BKV+row)*KSTP + c4*4], Klg + (size_t)(k0+row)*32 + c4*4);
            int vr = tid >> 4, vc = tid & 15;
            cpa16(&Vh[(nxt*(BKV/2)+vr)*VSTP + vc*4], Vhg + (size_t)(k0/2+vr)*64 + vc*4);
            cpa16(&Vl[(nxt*(BKV/2)+vr)*VSTP + vc*4], Vlg + (size_t)(k0/2+vr)*64 + vc*4);
            if (tid < 8) cpa16(&ms[nxt*BKV + tid*4], mrow + k0 + tid*4);
            CPCOMMIT();
            CPWAIT(1);
        } else {
            CPWAIT(0);
        }
        __syncthreads();

        const uint32_t* KhC = Kh + cur * BKV * KSTP;
        const uint32_t* KlC = Kl + cur * BKV * KSTP;
        const uint32_t* VhC = Vh + cur * (BKV/2) * VSTP;
        const uint32_t* VlC = Vl + cur * (BKV/2) * VSTP;
        const int*      msC = ms + cur * BKV;

        // ---- S = Q @ K^T ----
        float s[4][4];
        #pragma unroll
        for (int nt = 0; nt < 4; nt++)
            #pragma unroll
            for (int e = 0; e < 4; e++) s[nt][e] = 0.f;

        #pragma unroll
        for (int ks = 0; ks < 4; ks++) {
            int d0 = ks*8 + cq, d1 = ks*8 + 4 + cq;
            uint32_t bh[4][2], bl[4][2];
            #pragma unroll
            for (int nt = 0; nt < 4; nt++) {
                int nn = nt*8 + g;
                bh[nt][0] = KhC[nn*KSTP + d0];
                bh[nt][1] = KhC[nn*KSTP + d1];
                bl[nt][0] = KlC[nn*KSTP + d0];
                bl[nt][1] = KlC[nn*KSTP + d1];
            }
            #pragma unroll
            for (int nt = 0; nt < 4; nt++) {
                mmab(s[nt], qh[ks], bh[nt]);
                mmab(s[nt], ql[ks], bh[nt]);
                mmab(s[nt], qh[ks], bl[nt]);
            }
        }

        // ---- mask + online softmax ----
        float mx0 = -1e30f, mx1 = -1e30f;
        #pragma unroll
        for (int nt = 0; nt < 4; nt++) {
            #pragma unroll
            for (int j = 0; j < 2; j++) {
                int mv = msC[nt*8 + 2*cq + j];
                float v0 = mv ? s[nt][j]   : -1e30f;
                float v1 = mv ? s[nt][2+j] : -1e30f;
                s[nt][j] = v0; s[nt][2+j] = v1;
                mx0 = fmaxf(mx0, v0); mx1 = fmaxf(mx1, v1);
            }
        }
        mx0 = fmaxf(mx0, __shfl_xor_sync(0xffffffffu, mx0, 1));
        mx0 = fmaxf(mx0, __shfl_xor_sync(0xffffffffu, mx0, 2));
        mx1 = fmaxf(mx1, __shfl_xor_sync(0xffffffffu, mx1, 1));
        mx1 = fmaxf(mx1, __shfl_xor_sync(0xffffffffu, mx1, 2));

        float mn0 = fmaxf(mi[0], mx0), mn1 = fmaxf(mi[1], mx1);
        float cr0 = __expf(mi[0] - mn0), cr1 = __expf(mi[1] - mn1);
        float sum0 = 0.f, sum1 = 0.f;
        #pragma unroll
        for (int nt = 0; nt < 4; nt++) {
            s[nt][0] = __expf(s[nt][0] - mn0);
            s[nt][1] = __expf(s[nt][1] - mn0);
            s[nt][2] = __expf(s[nt][2] - mn1);
            s[nt][3] = __expf(s[nt][3] - mn1);
            sum0 += s[nt][0] + s[nt][1];
            sum1 += s[nt][2] + s[nt][3];
        }
        sum0 += __shfl_xor_sync(0xffffffffu, sum0, 1);
        sum0 += __shfl_xor_sync(0xffffffffu, sum0, 2);
        sum1 += __shfl_xor_sync(0xffffffffu, sum1, 1);
        sum1 += __shfl_xor_sync(0xffffffffu, sum1, 2);
        li[0] = li[0] * cr0 + sum0; mi[0] = mn0;
        li[1] = li[1] * cr1 + sum1; mi[1] = mn1;
        #pragma unroll
        for (int nt = 0; nt < 8; nt++) {
            acc[nt][0] *= cr0; acc[nt][1] *= cr0;
            acc[nt][2] *= cr1; acc[nt][3] *= cr1;
        }

        // ---- P fragments: register repack (A-frag == C-frag layout) ----
        uint32_t ph[2][4], pl[2][4];
        #pragma unroll
        for (int k2 = 0; k2 < 2; k2++) {
            split_pack(s[2*k2  ][0], s[2*k2  ][1], ph[k2][0], pl[k2][0]);
            split_pack(s[2*k2  ][2], s[2*k2  ][3], ph[k2][1], pl[k2][1]);
            split_pack(s[2*k2+1][0], s[2*k2+1][1], ph[k2][2], pl[k2][2]);
            split_pack(s[2*k2+1][2], s[2*k2+1][3], ph[k2][3], pl[k2][3]);
        }

        // ---- O += P @ V ----
        #pragma unroll
        for (int k2 = 0; k2 < 2; k2++) {
            int sp0 = k2*8 + cq, sp1 = k2*8 + 4 + cq;
            uint32_t vh[8][2], vl[8][2];
            #pragma unroll
            for (int nt = 0; nt < 8; nt++) {
                int dd = nt*8 + g;
                vh[nt][0] = VhC[sp0*VSTP + dd];
                vh[nt][1] = VhC[sp1*VSTP + dd];
                vl[nt][0] = VlC[sp0*VSTP + dd];
                vl[nt][1] = VlC[sp1*VSTP + dd];
            }
            #pragma unroll
            for (int nt = 0; nt < 8; nt++) {
                mmab(acc[nt], ph[k2], vh[nt]);
                mmab(acc[nt], pl[k2], vh[nt]);
                mmab(acc[nt], ph[k2], vl[nt]);
            }
        }
        __syncthreads();
    }

    // ---- epilogue ----
    float inv0 = 1.f / li[0], inv1 = 1.f / li[1];
    #pragma unroll
    for (int nt = 0; nt < 8; nt++) {
        int col = h * 64 + nt * 8 + 2 * cq;
        size_t r0 = (size_t)(n * SEQ + q0 + rb) * EMB + col;
        size_t r1 = (size_t)(n * SEQ + q0 + rb + 8) * EMB + col;
        *(float2*)&g_ao[r0] = make_float2(acc[nt][0]*inv0, acc[nt][1]*inv0);
        *(float2*)&g_ao[r1] = make_float2(acc[nt][2]*inv1, acc[nt][3]*inv1);
    }
}

// ============================================================
extern "C" void kernel_launch(void* const* d_in, const int* in_sizes, int n_in,
                              void* d_out, int out_size)
{
    const float* values = (const float*)d_in[0];
    const float* keys   = (const float*)d_in[1];
    const float* query  = (const float*)d_in[2];
    const int*   mask   = (const int*)  d_in[3];
    const float* Wv     = (const float*)d_in[4];
    const float* Wk     = (const float*)d_in[5];
    const float* Wq     = (const float*)d_in[6];
    const float* Wo     = (const float*)d_in[7];
    const float* bo     = (const float*)d_in[8];

    split_w<<<dim3(EMB*EMB/2/256, 4), 256>>>(Wv, Wk, Wq, Wo);

    cudaFuncSetAttribute(proj_kernel, cudaFuncAttributeMaxDynamicSharedMemorySize, GEMM_SMEM);
    proj_kernel<<<dim3(EMB/128, NROWS/128, 3), 256, GEMM_SMEM>>>(values, keys, query);

    cudaFuncSetAttribute(flash_kernel, cudaFuncAttributeMaxDynamicSharedMemorySize, FLASH_SMEM);
    flash_kernel<<<dim3(SEQ/BQF, NH), 256, FLASH_SMEM>>>(mask);

    cudaFuncSetAttribute(out_kernel, cudaFuncAttributeMaxDynamicSharedMemorySize, GEMM_SMEM);
    out_kernel<<<dim3(EMB/128, NROWS/128), 256, GEMM_SMEM>>>(bo, (float*)d_out);
}